// round 1
// baseline (speedup 1.0000x reference)
#include <cuda_runtime.h>

typedef unsigned long long ull;

#define BM 128
#define BN 128
#define BK 16
#define LDS_PAD 132   // 132 floats = 528B row stride, keeps 16B alignment

// ---------------- scratch (device globals: no allocations allowed) ----------
__device__ float g_q[8192 * 3072];     // 96 MB
__device__ float g_k[8192 * 3072];     // 96 MB
__device__ float g_v[8192 * 3072];     // 96 MB
__device__ float g_s[4 * 2048 * 2048]; // 64 MB  scores / probs
__device__ float g_ctx[8192 * 3072];   // 96 MB

// ---------------- packed f32x2 helpers (sm_100-family FFMA2 path) -----------
__device__ __forceinline__ ull pack2(float lo, float hi) {
    ull r; asm("mov.b64 %0, {%1, %2};" : "=l"(r) : "f"(lo), "f"(hi)); return r;
}
__device__ __forceinline__ void fma2(ull& d, ull a, ull b) {
    asm("fma.rn.f32x2 %0, %1, %2, %0;" : "+l"(d) : "l"(a), "l"(b));
}
__device__ __forceinline__ float2 unpack2(ull v) {
    float2 r; asm("mov.b64 {%0, %1}, %2;" : "=f"(r.x), "=f"(r.y) : "l"(v)); return r;
}

// ---------------------------------------------------------------------------
// C[m][n] = alpha * sum_k A[m][k] * (TB ? B[n][k] : B[k][n])  (+ bias[n])
// 128x128 CTA tile, BK=16, 256 threads, 8x8 per-thread microtile via FFMA2.
// All dims must be multiples of 128 (M,N) and 16 (K) — true for every call here.
// ---------------------------------------------------------------------------
template <bool TB>
__global__ void __launch_bounds__(256, 2)
gemm_kernel(const float* __restrict__ A, const float* __restrict__ B,
            float* __restrict__ C, const float* __restrict__ bias,
            int M, int N, int K, int lda, int ldb, int ldc, float alpha,
            long long sA, long long sB, long long sC)
{
    (void)M; (void)N;
    A += (long long)blockIdx.z * sA;
    B += (long long)blockIdx.z * sB;
    C += (long long)blockIdx.z * sC;

    const int tid = threadIdx.x;
    const int tx = tid & 15;   // column group
    const int ty = tid >> 4;   // row group
    const int m0 = blockIdx.y * BM;
    const int n0 = blockIdx.x * BN;

    __shared__ __align__(16) float As[BK][LDS_PAD]; // As[k][m]
    __shared__ __align__(16) float Bs[BK][LDS_PAD]; // Bs[k][n]

    // ---- global -> smem loader mappings ----
    const int lrow = tid >> 2;       // 0..63
    const int lc4  = (tid & 3) * 4;  // 0,4,8,12

    const float* Ap0 = A + (long long)(m0 + lrow) * lda + lc4;
    const float* Ap1 = Ap0 + (long long)64 * lda;

    const float* Bp0;
    const float* Bp1;
    int nbrow = 0, nbc4 = 0;
    if (TB) {
        Bp0 = B + (long long)(n0 + lrow) * ldb + lc4;
        Bp1 = Bp0 + (long long)64 * ldb;
    } else {
        nbrow = tid >> 5;          // 0..7
        nbc4  = (tid & 31) * 4;    // 0..124
        Bp0 = B + (long long)nbrow * ldb + n0 + nbc4;
        Bp1 = Bp0 + (long long)8 * ldb;
    }

    // prefetch tile 0
    float4 ra0 = *(const float4*)Ap0;
    float4 ra1 = *(const float4*)Ap1;
    float4 rb0 = *(const float4*)Bp0;
    float4 rb1 = *(const float4*)Bp1;
    Ap0 += BK; Ap1 += BK;
    if (TB) { Bp0 += BK; Bp1 += BK; }
    else    { Bp0 += (long long)BK * ldb; Bp1 += (long long)BK * ldb; }

    ull acc[4][8];
#pragma unroll
    for (int i = 0; i < 4; ++i)
#pragma unroll
        for (int j = 0; j < 8; ++j) acc[i][j] = 0ull;

    const int nk = K / BK;
    for (int kt = 0; kt < nk; ++kt) {
        // stage -> smem
        As[lc4 + 0][lrow] = ra0.x; As[lc4 + 1][lrow] = ra0.y;
        As[lc4 + 2][lrow] = ra0.z; As[lc4 + 3][lrow] = ra0.w;
        As[lc4 + 0][lrow + 64] = ra1.x; As[lc4 + 1][lrow + 64] = ra1.y;
        As[lc4 + 2][lrow + 64] = ra1.z; As[lc4 + 3][lrow + 64] = ra1.w;
        if (TB) {
            Bs[lc4 + 0][lrow] = rb0.x; Bs[lc4 + 1][lrow] = rb0.y;
            Bs[lc4 + 2][lrow] = rb0.z; Bs[lc4 + 3][lrow] = rb0.w;
            Bs[lc4 + 0][lrow + 64] = rb1.x; Bs[lc4 + 1][lrow + 64] = rb1.y;
            Bs[lc4 + 2][lrow + 64] = rb1.z; Bs[lc4 + 3][lrow + 64] = rb1.w;
        } else {
            *(float4*)&Bs[nbrow][nbc4]     = rb0;
            *(float4*)&Bs[nbrow + 8][nbc4] = rb1;
        }
        __syncthreads();

        // prefetch next tile while computing
        if (kt + 1 < nk) {
            ra0 = *(const float4*)Ap0; ra1 = *(const float4*)Ap1;
            rb0 = *(const float4*)Bp0; rb1 = *(const float4*)Bp1;
            Ap0 += BK; Ap1 += BK;
            if (TB) { Bp0 += BK; Bp1 += BK; }
            else    { Bp0 += (long long)BK * ldb; Bp1 += (long long)BK * ldb; }
        }

#pragma unroll
        for (int k = 0; k < BK; ++k) {
            // row pairs come packed for free from smem
            double2 da0 = *(const double2*)&As[k][ty * 4];
            double2 da1 = *(const double2*)&As[k][ty * 4 + 64];
            ull a2[4] = { __double_as_longlong(da0.x), __double_as_longlong(da0.y),
                          __double_as_longlong(da1.x), __double_as_longlong(da1.y) };
            float4 b0 = *(const float4*)&Bs[k][tx * 4];
            float4 b1 = *(const float4*)&Bs[k][tx * 4 + 64];
            ull bb[8] = { pack2(b0.x, b0.x), pack2(b0.y, b0.y),
                          pack2(b0.z, b0.z), pack2(b0.w, b0.w),
                          pack2(b1.x, b1.x), pack2(b1.y, b1.y),
                          pack2(b1.z, b1.z), pack2(b1.w, b1.w) };
#pragma unroll
            for (int rp = 0; rp < 4; ++rp)
#pragma unroll
                for (int c = 0; c < 8; ++c)
                    fma2(acc[rp][c], a2[rp], bb[c]);
        }
        __syncthreads();
    }

    // ---- epilogue: alpha, bias, store ----
    float4 bs0 = make_float4(0.f, 0.f, 0.f, 0.f), bs1 = bs0;
    if (bias) {
        bs0 = *(const float4*)&bias[n0 + tx * 4];
        bs1 = *(const float4*)&bias[n0 + tx * 4 + 64];
    }
#pragma unroll
    for (int rp = 0; rp < 4; ++rp) {
        const int r = m0 + ty * 4 + ((rp & 1) << 1) + ((rp >> 1) << 6);
        float2 v0 = unpack2(acc[rp][0]); float2 v1 = unpack2(acc[rp][1]);
        float2 v2 = unpack2(acc[rp][2]); float2 v3 = unpack2(acc[rp][3]);
        float2 v4 = unpack2(acc[rp][4]); float2 v5 = unpack2(acc[rp][5]);
        float2 v6 = unpack2(acc[rp][6]); float2 v7 = unpack2(acc[rp][7]);
        float4 lo0 = make_float4(fmaf(alpha, v0.x, bs0.x), fmaf(alpha, v1.x, bs0.y),
                                 fmaf(alpha, v2.x, bs0.z), fmaf(alpha, v3.x, bs0.w));
        float4 lo1 = make_float4(fmaf(alpha, v4.x, bs1.x), fmaf(alpha, v5.x, bs1.y),
                                 fmaf(alpha, v6.x, bs1.z), fmaf(alpha, v7.x, bs1.w));
        float4 hi0 = make_float4(fmaf(alpha, v0.y, bs0.x), fmaf(alpha, v1.y, bs0.y),
                                 fmaf(alpha, v2.y, bs0.z), fmaf(alpha, v3.y, bs0.w));
        float4 hi1 = make_float4(fmaf(alpha, v4.y, bs1.x), fmaf(alpha, v5.y, bs1.y),
                                 fmaf(alpha, v6.y, bs1.z), fmaf(alpha, v7.y, bs1.w));
        *(float4*)&C[(long long)r * ldc + n0 + tx * 4]            = lo0;
        *(float4*)&C[(long long)r * ldc + n0 + tx * 4 + 64]       = lo1;
        *(float4*)&C[(long long)(r + 1) * ldc + n0 + tx * 4]      = hi0;
        *(float4*)&C[(long long)(r + 1) * ldc + n0 + tx * 4 + 64] = hi1;
    }
}

// ---------------- row softmax over 2048 columns -----------------------------
__global__ void __launch_bounds__(256)
softmax2048(float* __restrict__ S)
{
    float* p = S + (long long)blockIdx.x * 2048;
    const int t = threadIdx.x;

    float4 x0 = *(const float4*)&p[t * 4];
    float4 x1 = *(const float4*)&p[1024 + t * 4];

    float m = fmaxf(fmaxf(fmaxf(x0.x, x0.y), fmaxf(x0.z, x0.w)),
                    fmaxf(fmaxf(x1.x, x1.y), fmaxf(x1.z, x1.w)));
#pragma unroll
    for (int o = 16; o > 0; o >>= 1) m = fmaxf(m, __shfl_xor_sync(0xffffffffu, m, o));

    __shared__ float red[8];
    if ((t & 31) == 0) red[t >> 5] = m;
    __syncthreads();
    m = fmaxf(fmaxf(fmaxf(red[0], red[1]), fmaxf(red[2], red[3])),
              fmaxf(fmaxf(red[4], red[5]), fmaxf(red[6], red[7])));
    __syncthreads();  // everyone done reading red before reuse

    float e0 = __expf(x0.x - m), e1 = __expf(x0.y - m);
    float e2 = __expf(x0.z - m), e3 = __expf(x0.w - m);
    float e4 = __expf(x1.x - m), e5 = __expf(x1.y - m);
    float e6 = __expf(x1.z - m), e7 = __expf(x1.w - m);

    float s = ((e0 + e1) + (e2 + e3)) + ((e4 + e5) + (e6 + e7));
#pragma unroll
    for (int o = 16; o > 0; o >>= 1) s += __shfl_xor_sync(0xffffffffu, s, o);
    if ((t & 31) == 0) red[t >> 5] = s;
    __syncthreads();
    float tot = ((red[0] + red[1]) + (red[2] + red[3])) +
                ((red[4] + red[5]) + (red[6] + red[7]));
    float inv = 1.0f / tot;

    *(float4*)&p[t * 4]        = make_float4(e0 * inv, e1 * inv, e2 * inv, e3 * inv);
    *(float4*)&p[1024 + t * 4] = make_float4(e4 * inv, e5 * inv, e6 * inv, e7 * inv);
}

// ---------------------------------------------------------------------------
extern "C" void kernel_launch(void* const* d_in, const int* in_sizes, int n_in,
                              void* d_out, int out_size)
{
    (void)in_sizes; (void)n_in; (void)out_size;
    const float* x  = (const float*)d_in[0];
    const float* Wq = (const float*)d_in[1];
    const float* bq = (const float*)d_in[2];
    const float* Wk = (const float*)d_in[3];
    const float* bk = (const float*)d_in[4];
    const float* Wv = (const float*)d_in[5];
    const float* bv = (const float*)d_in[6];
    const float* Wo = (const float*)d_in[7];
    const float* bo = (const float*)d_in[8];
    float* out = (float*)d_out;

    float *q, *k, *v, *s, *ctx;
    cudaGetSymbolAddress((void**)&q,   g_q);
    cudaGetSymbolAddress((void**)&k,   g_k);
    cudaGetSymbolAddress((void**)&v,   g_v);
    cudaGetSymbolAddress((void**)&s,   g_s);
    cudaGetSymbolAddress((void**)&ctx, g_ctx);

    const dim3 blk(256, 1, 1);

    // 1) QKV projections: [8192,1024] x [3072,1024]^T  (+bias)
    {
        dim3 g(3072 / BN, 8192 / BM, 1);
        gemm_kernel<true><<<g, blk>>>(x, Wq, q, bq, 8192, 3072, 1024,
                                      1024, 1024, 3072, 1.0f, 0, 0, 0);
        gemm_kernel<true><<<g, blk>>>(x, Wk, k, bk, 8192, 3072, 1024,
                                      1024, 1024, 3072, 1.0f, 0, 0, 0);
        gemm_kernel<true><<<g, blk>>>(x, Wv, v, bv, 8192, 3072, 1024,
                                      1024, 1024, 3072, 1.0f, 0, 0, 0);
    }
    // 2) scores = (Q Kᵀ) / sqrt(64), per batch
    {
        dim3 g(2048 / BN, 2048 / BM, 4);
        gemm_kernel<true><<<g, blk>>>(q, k, s, nullptr, 2048, 2048, 3072,
                                      3072, 3072, 2048, 0.125f,
                                      (long long)2048 * 3072,
                                      (long long)2048 * 3072,
                                      (long long)2048 * 2048);
    }
    // 3) softmax over last dim
    softmax2048<<<8192, 256>>>(s);
    // 4) ctx = P V, per batch (B not transposed)
    {
        dim3 g(3072 / BN, 2048 / BM, 4);
        gemm_kernel<false><<<g, blk>>>(s, v, ctx, nullptr, 2048, 3072, 2048,
                                       2048, 3072, 3072, 1.0f,
                                       (long long)2048 * 2048,
                                       (long long)2048 * 3072,
                                       (long long)2048 * 3072);
    }
    // 5) out = ctx Woᵀ + bo
    {
        dim3 g(1024 / BN, 8192 / BM, 1);
        gemm_kernel<true><<<g, blk>>>(ctx, Wo, out, bo, 8192, 1024, 3072,
                                      3072, 3072, 1024, 1.0f, 0, 0, 0);
    }
}

// round 3
// speedup vs baseline: 2.5092x; 2.5092x over previous
#include <cuda_runtime.h>
#include <cuda_bf16.h>
#include <cstdint>

typedef __nv_bfloat16 bf16;

// ---------------- scratch (device globals; allocation is forbidden) --------
__device__ bf16 g_xh[8192 * 1024], g_xl[8192 * 1024];
__device__ bf16 g_wh[3072 * 1024], g_wl[3072 * 1024];   // reused per weight
__device__ bf16 g_qh[8192 * 3072], g_ql[8192 * 3072];
__device__ bf16 g_kh[8192 * 3072], g_kl[8192 * 3072];
__device__ bf16 g_vh[8192 * 3072], g_vl[8192 * 3072];
__device__ float g_s[8192 * 2048];
__device__ bf16 g_ph[8192 * 2048], g_pl[8192 * 2048];
__device__ bf16 g_ch[8192 * 3072], g_cl[8192 * 3072];

// ---------------- helpers ---------------------------------------------------
__device__ __forceinline__ uint32_t smem_u32(const void* p) {
    uint32_t a;
    asm("{ .reg .u64 t; cvta.to.shared.u64 t, %1; cvt.u32.u64 %0, t; }"
        : "=r"(a) : "l"(p));
    return a;
}
__device__ __forceinline__ void cp16(uint32_t s, const void* g) {
    asm volatile("cp.async.cg.shared.global [%0], [%1], 16;" :: "r"(s), "l"(g));
}
__device__ __forceinline__ void cp_commit() {
    asm volatile("cp.async.commit_group;" ::: "memory");
}
__device__ __forceinline__ void cp_wait1() {
    asm volatile("cp.async.wait_group 1;" ::: "memory");
}
__device__ __forceinline__ void ldsm4(uint32_t* r, uint32_t a) {
    asm volatile("ldmatrix.sync.aligned.m8n8.x4.shared.b16 {%0,%1,%2,%3}, [%4];"
                 : "=r"(r[0]), "=r"(r[1]), "=r"(r[2]), "=r"(r[3]) : "r"(a));
}
__device__ __forceinline__ void ldsm4t(uint32_t* r, uint32_t a) {
    asm volatile("ldmatrix.sync.aligned.m8n8.x4.trans.shared.b16 {%0,%1,%2,%3}, [%4];"
                 : "=r"(r[0]), "=r"(r[1]), "=r"(r[2]), "=r"(r[3]) : "r"(a));
}
__device__ __forceinline__ void mma16816(float* d, const uint32_t* a, const uint32_t* b) {
    asm volatile("mma.sync.aligned.m16n8k16.row.col.f32.bf16.bf16.f32 "
                 "{%0,%1,%2,%3}, {%4,%5,%6,%7}, {%8,%9}, {%0,%1,%2,%3};"
                 : "+f"(d[0]), "+f"(d[1]), "+f"(d[2]), "+f"(d[3])
                 : "r"(a[0]), "r"(a[1]), "r"(a[2]), "r"(a[3]), "r"(b[0]), "r"(b[1]));
}
__device__ __forceinline__ void split2(float x, bf16& h, bf16& l) {
    h = __float2bfloat16(x);
    l = __float2bfloat16(x - __bfloat162float(h));
}

// ---------------------------------------------------------------------------
// D[m][n] = alpha * sum_k A[m][k] * B^T[n][k]  (+ bias[n])
//   TRB=false: B given as [n][k] (k contiguous)    -> plain ldmatrix
//   TRB=true : B given as [k][n] (n contiguous, V) -> ldmatrix.trans
//   MODE=0: write fp32 Cf;  MODE=1: write bf16 hi/lo split Ch/Cl
// CTA 128x128, BK=32, 256 threads, 3-stage cp.async pipeline.
// ---------------------------------------------------------------------------
#define STG_B 32768
#define NSTG  3
#define SMEM_DYN (NSTG * STG_B)

template <bool TRB, int MODE>
__global__ void __launch_bounds__(256, 2)
mma_gemm(const bf16* __restrict__ Ah, const bf16* __restrict__ Al, int ldA, long long sAz,
         const bf16* __restrict__ Bh, const bf16* __restrict__ Bl, int ldB, long long sBz,
         float* __restrict__ Cf, bf16* __restrict__ Ch, bf16* __restrict__ Cl,
         int ldC, long long sCz, const float* __restrict__ bias, float alpha, int K)
{
    extern __shared__ char smem[];
    __shared__ float bias_s[128];
    const uint32_t sb = smem_u32(smem);
    const int tid = threadIdx.x, lane = tid & 31, wid = tid >> 5;
    const int m0 = blockIdx.y * 128, n0 = blockIdx.x * 128;
    const long long z = blockIdx.z;

    Ah += z * sAz; Al += z * sAz;
    Bh += z * sBz; Bl += z * sBz;
    if constexpr (MODE == 0) { Cf += z * sCz; }
    else                     { Ch += z * sCz; Cl += z * sCz; }

    if (tid < 128) bias_s[tid] = bias ? bias[n0 + tid] : 0.0f;

    // ---- loader precompute (each thread: 8 x 16B cp.async per stage) ------
    const int arow = tid >> 2, ac16 = tid & 3;
    const uint32_t sAoff = (uint32_t)arow * 64u + (uint32_t)((ac16 ^ ((arow >> 1) & 3)) << 4);
    const size_t ldAs = (size_t)ldA, ldBs = (size_t)ldB;
    const bf16* pAh = Ah + (size_t)(m0 + arow) * ldAs + ac16 * 8;
    const bf16* pAl = Al + (size_t)(m0 + arow) * ldAs + ac16 * 8;
    const bf16 *pBh, *pBl;
    uint32_t sBoff;
    if constexpr (!TRB) {
        pBh = Bh + (size_t)(n0 + arow) * ldBs + ac16 * 8;
        pBl = Bl + (size_t)(n0 + arow) * ldBs + ac16 * 8;
        sBoff = sAoff;
    } else {
        const int kB = tid >> 4, c16B = tid & 15;
        pBh = Bh + (size_t)kB * ldBs + n0 + c16B * 8;
        pBl = Bl + (size_t)kB * ldBs + n0 + c16B * 8;
        sBoff = (uint32_t)kB * 256u + (uint32_t)((c16B ^ (kB & 7)) << 4);
    }

    auto load_stage = [&](int slot, int kt) {
        const uint32_t s0 = sb + (uint32_t)slot * STG_B;
        const size_t k0 = (size_t)kt * 32;
#pragma unroll
        for (int i = 0; i < 2; ++i) {
            cp16(s0 + i * 4096u + sAoff,         pAh + k0 + (size_t)(i * 64) * ldAs);
            cp16(s0 + 8192u + i * 4096u + sAoff, pAl + k0 + (size_t)(i * 64) * ldAs);
        }
        if constexpr (!TRB) {
#pragma unroll
            for (int i = 0; i < 2; ++i) {
                cp16(s0 + 16384u + i * 4096u + sBoff, pBh + k0 + (size_t)(i * 64) * ldBs);
                cp16(s0 + 24576u + i * 4096u + sBoff, pBl + k0 + (size_t)(i * 64) * ldBs);
            }
        } else {
#pragma unroll
            for (int i = 0; i < 2; ++i) {
                cp16(s0 + 16384u + i * 4096u + sBoff, pBh + (k0 + i * 16) * ldBs);
                cp16(s0 + 24576u + i * 4096u + sBoff, pBl + (k0 + i * 16) * ldBs);
            }
        }
    };

    // ---- per-warp fragment addressing -------------------------------------
    const int wm = (wid & 3) * 32, wn = (wid >> 2) * 64;
    const int rowAf = wm + (lane & 15);
    const uint32_t swzA = (uint32_t)((rowAf >> 1) & 3);
    const int nrow = wn + (lane & 7) + 8 * (lane >> 4);       // NT path
    const uint32_t swzB = (uint32_t)((nrow >> 1) & 3);

    float C[2][8][4];
#pragma unroll
    for (int a = 0; a < 2; ++a)
#pragma unroll
        for (int b = 0; b < 8; ++b)
#pragma unroll
            for (int c = 0; c < 4; ++c) C[a][b][c] = 0.0f;

    const int nk = K >> 5;
    load_stage(0, 0); cp_commit();
    load_stage(1, 1); cp_commit();

    for (int kt = 0; kt < nk; ++kt) {
        cp_wait1();
        __syncthreads();
        if (kt + 2 < nk) load_stage((kt + 2) % NSTG, kt + 2);
        cp_commit();

        const uint32_t s0 = sb + (uint32_t)(kt % NSTG) * STG_B;
#pragma unroll
        for (int ks = 0; ks < 2; ++ks) {
            uint32_t aH[2][4], aL[2][4];
            const uint32_t kcA = (uint32_t)(ks * 2 + (lane >> 4));
#pragma unroll
            for (int mf = 0; mf < 2; ++mf) {
                const uint32_t off = (uint32_t)(rowAf + 16 * mf) * 64u + ((kcA ^ swzA) << 4);
                ldsm4(aH[mf], s0 + off);
                ldsm4(aL[mf], s0 + 8192u + off);
            }

#pragma unroll
            for (int nh = 0; nh < 2; ++nh) {
                uint32_t bb[2][4];
                // ---- Bh fragments ----
                if constexpr (!TRB) {
                    const uint32_t kcB = (uint32_t)(ks * 2 + ((lane >> 3) & 1));
#pragma unroll
                    for (int j = 0; j < 2; ++j) {
                        const int nf2 = nh * 2 + j;
                        const uint32_t off = 16384u + (uint32_t)(nrow + 16 * nf2) * 64u +
                                             ((kcB ^ swzB) << 4);
                        ldsm4(bb[j], s0 + off);
                    }
                } else {
                    const uint32_t krow = (uint32_t)(ks * 16 + 8 * ((lane >> 3) & 1) + (lane & 7));
                    const uint32_t rowo = 16384u + krow * 256u;
#pragma unroll
                    for (int j = 0; j < 2; ++j) {
                        const uint32_t c16 = (uint32_t)((wn >> 3) + (lane >> 4) + (nh * 2 + j) * 2);
                        ldsm4t(bb[j], s0 + rowo + ((c16 ^ (uint32_t)(lane & 7)) << 4));
                    }
                }
#pragma unroll
                for (int mf = 0; mf < 2; ++mf)
#pragma unroll
                    for (int j = 0; j < 2; ++j) {
                        mma16816(C[mf][nh * 4 + j * 2 + 0], aH[mf], &bb[j][0]);
                        mma16816(C[mf][nh * 4 + j * 2 + 1], aH[mf], &bb[j][2]);
                    }
#pragma unroll
                for (int mf = 0; mf < 2; ++mf)
#pragma unroll
                    for (int j = 0; j < 2; ++j) {
                        mma16816(C[mf][nh * 4 + j * 2 + 0], aL[mf], &bb[j][0]);
                        mma16816(C[mf][nh * 4 + j * 2 + 1], aL[mf], &bb[j][2]);
                    }
                // ---- Bl fragments (reuse bb), term Ah*Bl ----
                if constexpr (!TRB) {
                    const uint32_t kcB = (uint32_t)(ks * 2 + ((lane >> 3) & 1));
#pragma unroll
                    for (int j = 0; j < 2; ++j) {
                        const int nf2 = nh * 2 + j;
                        const uint32_t off = 24576u + (uint32_t)(nrow + 16 * nf2) * 64u +
                                             ((kcB ^ swzB) << 4);
                        ldsm4(bb[j], s0 + off);
                    }
                } else {
                    const uint32_t krow = (uint32_t)(ks * 16 + 8 * ((lane >> 3) & 1) + (lane & 7));
                    const uint32_t rowo = 24576u + krow * 256u;
#pragma unroll
                    for (int j = 0; j < 2; ++j) {
                        const uint32_t c16 = (uint32_t)((wn >> 3) + (lane >> 4) + (nh * 2 + j) * 2);
                        ldsm4t(bb[j], s0 + rowo + ((c16 ^ (uint32_t)(lane & 7)) << 4));
                    }
                }
#pragma unroll
                for (int mf = 0; mf < 2; ++mf)
#pragma unroll
                    for (int j = 0; j < 2; ++j) {
                        mma16816(C[mf][nh * 4 + j * 2 + 0], aH[mf], &bb[j][0]);
                        mma16816(C[mf][nh * 4 + j * 2 + 1], aH[mf], &bb[j][2]);
                    }
            }
        }
    }

    // ---- epilogue ----------------------------------------------------------
    const int mb = m0 + wm + (lane >> 2);
    const int nbl = wn + 2 * (lane & 3);
#pragma unroll
    for (int mf = 0; mf < 2; ++mf) {
        const size_t r0 = (size_t)(mb + 16 * mf);
#pragma unroll
        for (int nf = 0; nf < 8; ++nf) {
            const int cloc = nbl + nf * 8;
            const int c = n0 + cloc;
            const float b0 = bias_s[cloc], b1 = bias_s[cloc + 1];
            const float v0 = C[mf][nf][0] * alpha + b0;
            const float v1 = C[mf][nf][1] * alpha + b1;
            const float v2 = C[mf][nf][2] * alpha + b0;
            const float v3 = C[mf][nf][3] * alpha + b1;
            if constexpr (MODE == 0) {
                *(float2*)&Cf[r0 * ldC + c]       = make_float2(v0, v1);
                *(float2*)&Cf[(r0 + 8) * ldC + c] = make_float2(v2, v3);
            } else {
                bf16 h0, l0, h1, l1, h2, l2, h3, l3;
                split2(v0, h0, l0); split2(v1, h1, l1);
                split2(v2, h2, l2); split2(v3, h3, l3);
                *(__nv_bfloat162*)&Ch[r0 * ldC + c]       = __nv_bfloat162(h0, h1);
                *(__nv_bfloat162*)&Cl[r0 * ldC + c]       = __nv_bfloat162(l0, l1);
                *(__nv_bfloat162*)&Ch[(r0 + 8) * ldC + c] = __nv_bfloat162(h2, h3);
                *(__nv_bfloat162*)&Cl[(r0 + 8) * ldC + c] = __nv_bfloat162(l2, l3);
            }
        }
    }
}

// ---------------- fp32 -> bf16 hi/lo split ----------------------------------
__global__ void __launch_bounds__(256)
split_kernel(const float* __restrict__ in, bf16* __restrict__ hi,
             bf16* __restrict__ lo, int n4)
{
    const int i = blockIdx.x * 256 + threadIdx.x;
    if (i >= n4) return;
    const float4 x = ((const float4*)in)[i];
    bf16 h0, h1, h2, h3, l0, l1, l2, l3;
    split2(x.x, h0, l0); split2(x.y, h1, l1);
    split2(x.z, h2, l2); split2(x.w, h3, l3);
    ((__nv_bfloat162*)hi)[2 * i]     = __nv_bfloat162(h0, h1);
    ((__nv_bfloat162*)hi)[2 * i + 1] = __nv_bfloat162(h2, h3);
    ((__nv_bfloat162*)lo)[2 * i]     = __nv_bfloat162(l0, l1);
    ((__nv_bfloat162*)lo)[2 * i + 1] = __nv_bfloat162(l2, l3);
}

// ---------------- softmax over 2048 cols -> bf16 hi/lo probs ----------------
__global__ void __launch_bounds__(256)
softmax_split(const float* __restrict__ S, bf16* __restrict__ ph, bf16* __restrict__ pl)
{
    const long long row = blockIdx.x;
    const float* p = S + row * 2048;
    const int t = threadIdx.x;

    float4 x0 = *(const float4*)&p[t * 4];
    float4 x1 = *(const float4*)&p[1024 + t * 4];

    float m = fmaxf(fmaxf(fmaxf(x0.x, x0.y), fmaxf(x0.z, x0.w)),
                    fmaxf(fmaxf(x1.x, x1.y), fmaxf(x1.z, x1.w)));
#pragma unroll
    for (int o = 16; o > 0; o >>= 1) m = fmaxf(m, __shfl_xor_sync(0xffffffffu, m, o));
    __shared__ float red[8];
    if ((t & 31) == 0) red[t >> 5] = m;
    __syncthreads();
    m = fmaxf(fmaxf(fmaxf(red[0], red[1]), fmaxf(red[2], red[3])),
              fmaxf(fmaxf(red[4], red[5]), fmaxf(red[6], red[7])));
    __syncthreads();

    float e[8];
    e[0] = __expf(x0.x - m); e[1] = __expf(x0.y - m);
    e[2] = __expf(x0.z - m); e[3] = __expf(x0.w - m);
    e[4] = __expf(x1.x - m); e[5] = __expf(x1.y - m);
    e[6] = __expf(x1.z - m); e[7] = __expf(x1.w - m);

    float s = ((e[0] + e[1]) + (e[2] + e[3])) + ((e[4] + e[5]) + (e[6] + e[7]));
#pragma unroll
    for (int o = 16; o > 0; o >>= 1) s += __shfl_xor_sync(0xffffffffu, s, o);
    if ((t & 31) == 0) red[t >> 5] = s;
    __syncthreads();
    const float inv = 1.0f / (((red[0] + red[1]) + (red[2] + red[3])) +
                              ((red[4] + red[5]) + (red[6] + red[7])));

    bf16* hp = ph + row * 2048;
    bf16* lp = pl + row * 2048;
#pragma unroll
    for (int g = 0; g < 2; ++g) {
        bf16 hh[4], ll[4];
#pragma unroll
        for (int j = 0; j < 4; ++j) split2(e[g * 4 + j] * inv, hh[j], ll[j]);
        const int base = g * 1024 + t * 4;
        *(__nv_bfloat162*)&hp[base]     = __nv_bfloat162(hh[0], hh[1]);
        *(__nv_bfloat162*)&hp[base + 2] = __nv_bfloat162(hh[2], hh[3]);
        *(__nv_bfloat162*)&lp[base]     = __nv_bfloat162(ll[0], ll[1]);
        *(__nv_bfloat162*)&lp[base + 2] = __nv_bfloat162(ll[2], ll[3]);
    }
}

// ---------------------------------------------------------------------------
extern "C" void kernel_launch(void* const* d_in, const int* in_sizes, int n_in,
                              void* d_out, int out_size)
{
    (void)in_sizes; (void)n_in; (void)out_size;
    const float* x  = (const float*)d_in[0];
    const float* Wq = (const float*)d_in[1];
    const float* bq = (const float*)d_in[2];
    const float* Wk = (const float*)d_in[3];
    const float* bk = (const float*)d_in[4];
    const float* Wv = (const float*)d_in[5];
    const float* bv = (const float*)d_in[6];
    const float* Wo = (const float*)d_in[7];
    const float* bo = (const float*)d_in[8];
    float* out = (float*)d_out;

    bf16 *xh, *xl, *wh, *wl, *qh, *ql, *kh, *kl, *vh, *vl, *ph, *pl, *ch, *cl;
    float* s;
    cudaGetSymbolAddress((void**)&xh, g_xh); cudaGetSymbolAddress((void**)&xl, g_xl);
    cudaGetSymbolAddress((void**)&wh, g_wh); cudaGetSymbolAddress((void**)&wl, g_wl);
    cudaGetSymbolAddress((void**)&qh, g_qh); cudaGetSymbolAddress((void**)&ql, g_ql);
    cudaGetSymbolAddress((void**)&kh, g_kh); cudaGetSymbolAddress((void**)&kl, g_kl);
    cudaGetSymbolAddress((void**)&vh, g_vh); cudaGetSymbolAddress((void**)&vl, g_vl);
    cudaGetSymbolAddress((void**)&s, g_s);
    cudaGetSymbolAddress((void**)&ph, g_ph); cudaGetSymbolAddress((void**)&pl, g_pl);
    cudaGetSymbolAddress((void**)&ch, g_ch); cudaGetSymbolAddress((void**)&cl, g_cl);

    cudaFuncSetAttribute(mma_gemm<false, 0>, cudaFuncAttributeMaxDynamicSharedMemorySize, SMEM_DYN);
    cudaFuncSetAttribute(mma_gemm<false, 1>, cudaFuncAttributeMaxDynamicSharedMemorySize, SMEM_DYN);
    cudaFuncSetAttribute(mma_gemm<true, 1>,  cudaFuncAttributeMaxDynamicSharedMemorySize, SMEM_DYN);

    const long long QS = 2048LL * 3072, SS = 2048LL * 2048;

    // split x
    split_kernel<<<8192, 256>>>(x, xh, xl, 8192 * 1024 / 4);

    // Q = x Wq^T + bq -> split
    split_kernel<<<3072, 256>>>(Wq, wh, wl, 3072 * 1024 / 4);
    mma_gemm<false, 1><<<dim3(24, 64, 1), 256, SMEM_DYN>>>(
        xh, xl, 1024, 0, wh, wl, 1024, 0,
        nullptr, qh, ql, 3072, 0, bq, 1.0f, 1024);

    // K
    split_kernel<<<3072, 256>>>(Wk, wh, wl, 3072 * 1024 / 4);
    mma_gemm<false, 1><<<dim3(24, 64, 1), 256, SMEM_DYN>>>(
        xh, xl, 1024, 0, wh, wl, 1024, 0,
        nullptr, kh, kl, 3072, 0, bk, 1.0f, 1024);

    // V (natural [seq][e] layout; consumed k-major by the PV GEMM)
    split_kernel<<<3072, 256>>>(Wv, wh, wl, 3072 * 1024 / 4);
    mma_gemm<false, 1><<<dim3(24, 64, 1), 256, SMEM_DYN>>>(
        xh, xl, 1024, 0, wh, wl, 1024, 0,
        nullptr, vh, vl, 3072, 0, bv, 1.0f, 1024);

    // scores = (Q K^T) / 8, per batch
    mma_gemm<false, 0><<<dim3(16, 16, 4), 256, SMEM_DYN>>>(
        qh, ql, 3072, QS, kh, kl, 3072, QS,
        s, nullptr, nullptr, 2048, SS, nullptr, 0.125f, 3072);

    // softmax -> split probs
    softmax_split<<<8192, 256>>>(s, ph, pl);

    // ctx = P V, per batch (V loaded k-major, ldmatrix.trans) -> split
    mma_gemm<true, 1><<<dim3(24, 16, 4), 256, SMEM_DYN>>>(
        ph, pl, 2048, SS, vh, vl, 3072, QS,
        nullptr, ch, cl, 3072, QS, nullptr, 1.0f, 2048);

    // out = ctx Wo^T + bo
    split_kernel<<<3072, 256>>>(Wo, wh, wl, 1024 * 3072 / 4);
    mma_gemm<false, 0><<<dim3(8, 64, 1), 256, SMEM_DYN>>>(
        ch, cl, 3072, 0, wh, wl, 3072, 0,
        out, nullptr, nullptr, 1024, 0, bo, 1.0f, 3072);
}

// round 4
// speedup vs baseline: 6.2818x; 2.5035x over previous
#include <cuda_runtime.h>
#include <cuda_bf16.h>
#include <cstdint>

typedef __nv_bfloat16 bf16;

// ---------------- scratch (device globals; allocation is forbidden) --------
__device__ bf16 g_xh[8192 * 1024], g_xl[8192 * 1024];
__device__ bf16 g_w1h[3072 * 1024], g_w1l[3072 * 1024];  // Wq, later Wo
__device__ bf16 g_w2h[3072 * 1024], g_w2l[3072 * 1024];  // Wk, later Wv
__device__ float g_part[4 * 1024 * 1024];                // split-K partials
__device__ bf16 g_mh[1024 * 1024], g_ml[1024 * 1024];    // M = Wq^T Wk
__device__ bf16 g_nh[1024 * 1024], g_nl[1024 * 1024];    // N = Wo Wv
__device__ bf16 g_xmh[8192 * 1024], g_xml[8192 * 1024];  // X*M
__device__ float g_s[8192 * 2048];                       // scores
__device__ bf16 g_ph[8192 * 2048], g_pl[8192 * 2048];    // probs
__device__ bf16 g_c2h[8192 * 1024], g_c2l[8192 * 1024];  // P*X
__device__ float g_tvec[1024];   // Wk^T bq
__device__ float g_bvec[8192];   // X * tvec
__device__ float g_dvec[1024];   // Wo bv + bo

// ---------------- helpers ---------------------------------------------------
__device__ __forceinline__ uint32_t smem_u32(const void* p) {
    uint32_t a;
    asm("{ .reg .u64 t; cvta.to.shared.u64 t, %1; cvt.u32.u64 %0, t; }"
        : "=r"(a) : "l"(p));
    return a;
}
__device__ __forceinline__ void cp16(uint32_t s, const void* g) {
    asm volatile("cp.async.cg.shared.global [%0], [%1], 16;" :: "r"(s), "l"(g));
}
__device__ __forceinline__ void cp_commit() {
    asm volatile("cp.async.commit_group;" ::: "memory");
}
__device__ __forceinline__ void cp_wait1() {
    asm volatile("cp.async.wait_group 1;" ::: "memory");
}
__device__ __forceinline__ void ldsm4(uint32_t* r, uint32_t a) {
    asm volatile("ldmatrix.sync.aligned.m8n8.x4.shared.b16 {%0,%1,%2,%3}, [%4];"
                 : "=r"(r[0]), "=r"(r[1]), "=r"(r[2]), "=r"(r[3]) : "r"(a));
}
__device__ __forceinline__ void ldsm4t(uint32_t* r, uint32_t a) {
    asm volatile("ldmatrix.sync.aligned.m8n8.x4.trans.shared.b16 {%0,%1,%2,%3}, [%4];"
                 : "=r"(r[0]), "=r"(r[1]), "=r"(r[2]), "=r"(r[3]) : "r"(a));
}
__device__ __forceinline__ void mma16816(float* d, const uint32_t* a, const uint32_t* b) {
    asm volatile("mma.sync.aligned.m16n8k16.row.col.f32.bf16.bf16.f32 "
                 "{%0,%1,%2,%3}, {%4,%5,%6,%7}, {%8,%9}, {%0,%1,%2,%3};"
                 : "+f"(d[0]), "+f"(d[1]), "+f"(d[2]), "+f"(d[3])
                 : "r"(a[0]), "r"(a[1]), "r"(a[2]), "r"(a[3]), "r"(b[0]), "r"(b[1]));
}
__device__ __forceinline__ void split2(float x, bf16& h, bf16& l) {
    h = __float2bfloat16(x);
    l = __float2bfloat16(x - __bfloat162float(h));
}

// ---------------------------------------------------------------------------
// D[m][n] = alpha * sum_k A[m][k] * B^T[n][k]  (+ bias[n])
//   TRA: A given as [k][m] (m contiguous) -> ldmatrix.trans for A fragments
//   TRB: B given as [k][n] (n contiguous) -> ldmatrix.trans for B fragments
//   MODE=0: write fp32 Cf;  MODE=1: write bf16 hi/lo split Ch/Cl
// CTA 128x128, BK=32, 256 threads, 3-stage cp.async pipeline.
// z-offsets (sAz/sBz/sCz) are generic linear element strides: used for batch
// OR split-K slicing (caller picks strides; K = per-launch reduction length).
// ---------------------------------------------------------------------------
#define STG_B 32768
#define NSTG  3
#define SMEM_DYN (NSTG * STG_B)

template <bool TRA, bool TRB, int MODE>
__global__ void __launch_bounds__(256, 2)
mma_gemm(const bf16* __restrict__ Ah, const bf16* __restrict__ Al, int ldA, long long sAz,
         const bf16* __restrict__ Bh, const bf16* __restrict__ Bl, int ldB, long long sBz,
         float* __restrict__ Cf, bf16* __restrict__ Ch, bf16* __restrict__ Cl,
         int ldC, long long sCz, const float* __restrict__ bias, float alpha, int K)
{
    extern __shared__ char smem[];
    __shared__ float bias_s[128];
    const uint32_t sb = smem_u32(smem);
    const int tid = threadIdx.x, lane = tid & 31, wid = tid >> 5;
    const int m0 = blockIdx.y * 128, n0 = blockIdx.x * 128;
    const long long z = blockIdx.z;

    Ah += z * sAz; Al += z * sAz;
    Bh += z * sBz; Bl += z * sBz;
    if constexpr (MODE == 0) { Cf += z * sCz; }
    else                     { Ch += z * sCz; Cl += z * sCz; }

    if (tid < 128) bias_s[tid] = bias ? bias[n0 + tid] : 0.0f;

    const size_t ldAs = (size_t)ldA, ldBs = (size_t)ldB;

    // ---- loader precompute ------------------------------------------------
    const int arow = tid >> 2, ac16 = tid & 3;     // NT mapping
    const int krowL = tid >> 4, kc16 = tid & 15;   // trans mapping
    const bf16 *pAh, *pAl;
    uint32_t sAoff;
    if constexpr (!TRA) {
        pAh = Ah + (size_t)(m0 + arow) * ldAs + ac16 * 8;
        pAl = Al + (size_t)(m0 + arow) * ldAs + ac16 * 8;
        sAoff = (uint32_t)arow * 64u + (uint32_t)((ac16 ^ ((arow >> 1) & 3)) << 4);
    } else {
        pAh = Ah + (size_t)krowL * ldAs + m0 + kc16 * 8;
        pAl = Al + (size_t)krowL * ldAs + m0 + kc16 * 8;
        sAoff = (uint32_t)krowL * 256u + (uint32_t)((kc16 ^ (krowL & 7)) << 4);
    }
    const bf16 *pBh, *pBl;
    uint32_t sBoff;
    if constexpr (!TRB) {
        pBh = Bh + (size_t)(n0 + arow) * ldBs + ac16 * 8;
        pBl = Bl + (size_t)(n0 + arow) * ldBs + ac16 * 8;
        sBoff = (uint32_t)arow * 64u + (uint32_t)((ac16 ^ ((arow >> 1) & 3)) << 4);
    } else {
        pBh = Bh + (size_t)krowL * ldBs + n0 + kc16 * 8;
        pBl = Bl + (size_t)krowL * ldBs + n0 + kc16 * 8;
        sBoff = (uint32_t)krowL * 256u + (uint32_t)((kc16 ^ (krowL & 7)) << 4);
    }

    auto load_stage = [&](int slot, int kt) {
        const uint32_t s0 = sb + (uint32_t)slot * STG_B;
        const size_t k0 = (size_t)kt * 32;
#pragma unroll
        for (int i = 0; i < 2; ++i) {
            if constexpr (!TRA) {
                cp16(s0 + i * 4096u + sAoff,         pAh + k0 + (size_t)(i * 64) * ldAs);
                cp16(s0 + 8192u + i * 4096u + sAoff, pAl + k0 + (size_t)(i * 64) * ldAs);
            } else {
                cp16(s0 + i * 4096u + sAoff,         pAh + (k0 + i * 16) * ldAs);
                cp16(s0 + 8192u + i * 4096u + sAoff, pAl + (k0 + i * 16) * ldAs);
            }
        }
#pragma unroll
        for (int i = 0; i < 2; ++i) {
            if constexpr (!TRB) {
                cp16(s0 + 16384u + i * 4096u + sBoff, pBh + k0 + (size_t)(i * 64) * ldBs);
                cp16(s0 + 24576u + i * 4096u + sBoff, pBl + k0 + (size_t)(i * 64) * ldBs);
            } else {
                cp16(s0 + 16384u + i * 4096u + sBoff, pBh + (k0 + i * 16) * ldBs);
                cp16(s0 + 24576u + i * 4096u + sBoff, pBl + (k0 + i * 16) * ldBs);
            }
        }
    };

    // ---- per-warp fragment addressing -------------------------------------
    const int wm = (wid & 3) * 32, wn = (wid >> 2) * 64;
    const int rowAf = wm + (lane & 15);
    const uint32_t swzA = (uint32_t)((rowAf >> 1) & 3);
    const int nrow = wn + (lane & 7) + 8 * (lane >> 4);
    const uint32_t swzB = (uint32_t)((nrow >> 1) & 3);

    float C[2][8][4];
#pragma unroll
    for (int a = 0; a < 2; ++a)
#pragma unroll
        for (int b = 0; b < 8; ++b)
#pragma unroll
            for (int c = 0; c < 4; ++c) C[a][b][c] = 0.0f;

    const int nk = K >> 5;
    load_stage(0, 0); cp_commit();
    load_stage(1, 1); cp_commit();

    for (int kt = 0; kt < nk; ++kt) {
        cp_wait1();
        __syncthreads();
        if (kt + 2 < nk) load_stage((kt + 2) % NSTG, kt + 2);
        cp_commit();

        const uint32_t s0 = sb + (uint32_t)(kt % NSTG) * STG_B;
#pragma unroll
        for (int ks = 0; ks < 2; ++ks) {
            uint32_t aH[2][4], aL[2][4];
            if constexpr (!TRA) {
                const uint32_t kcA = (uint32_t)(ks * 2 + (lane >> 4));
#pragma unroll
                for (int mf = 0; mf < 2; ++mf) {
                    const uint32_t off = (uint32_t)(rowAf + 16 * mf) * 64u + ((kcA ^ swzA) << 4);
                    ldsm4(aH[mf], s0 + off);
                    ldsm4(aL[mf], s0 + 8192u + off);
                }
            } else {
                const uint32_t krow = (uint32_t)(ks * 16 + 8 * (lane >> 4) + (lane & 7));
                const uint32_t rowo = krow * 256u;
#pragma unroll
                for (int mf = 0; mf < 2; ++mf) {
                    const uint32_t c16 = (uint32_t)((wm >> 3) + 2 * mf + ((lane >> 3) & 1));
                    const uint32_t off = rowo + ((c16 ^ (uint32_t)(lane & 7)) << 4);
                    ldsm4t(aH[mf], s0 + off);
                    ldsm4t(aL[mf], s0 + 8192u + off);
                }
            }

#pragma unroll
            for (int nh = 0; nh < 2; ++nh) {
                uint32_t bb[2][4];
                // ---- Bh fragments: terms Ah*Bh + Al*Bh ----
                if constexpr (!TRB) {
                    const uint32_t kcB = (uint32_t)(ks * 2 + ((lane >> 3) & 1));
#pragma unroll
                    for (int j = 0; j < 2; ++j) {
                        const int nf2 = nh * 2 + j;
                        const uint32_t off = 16384u + (uint32_t)(nrow + 16 * nf2) * 64u +
                                             ((kcB ^ swzB) << 4);
                        ldsm4(bb[j], s0 + off);
                    }
                } else {
                    const uint32_t krow = (uint32_t)(ks * 16 + 8 * ((lane >> 3) & 1) + (lane & 7));
                    const uint32_t rowo = 16384u + krow * 256u;
#pragma unroll
                    for (int j = 0; j < 2; ++j) {
                        const uint32_t c16 = (uint32_t)((wn >> 3) + (lane >> 4) + (nh * 2 + j) * 2);
                        ldsm4t(bb[j], s0 + rowo + ((c16 ^ (uint32_t)(lane & 7)) << 4));
                    }
                }
#pragma unroll
                for (int mf = 0; mf < 2; ++mf)
#pragma unroll
                    for (int j = 0; j < 2; ++j) {
                        mma16816(C[mf][nh * 4 + j * 2 + 0], aH[mf], &bb[j][0]);
                        mma16816(C[mf][nh * 4 + j * 2 + 1], aH[mf], &bb[j][2]);
                    }
#pragma unroll
                for (int mf = 0; mf < 2; ++mf)
#pragma unroll
                    for (int j = 0; j < 2; ++j) {
                        mma16816(C[mf][nh * 4 + j * 2 + 0], aL[mf], &bb[j][0]);
                        mma16816(C[mf][nh * 4 + j * 2 + 1], aL[mf], &bb[j][2]);
                    }
                // ---- Bl fragments: term Ah*Bl ----
                if constexpr (!TRB) {
                    const uint32_t kcB = (uint32_t)(ks * 2 + ((lane >> 3) & 1));
#pragma unroll
                    for (int j = 0; j < 2; ++j) {
                        const int nf2 = nh * 2 + j;
                        const uint32_t off = 24576u + (uint32_t)(nrow + 16 * nf2) * 64u +
                                             ((kcB ^ swzB) << 4);
                        ldsm4(bb[j], s0 + off);
                    }
                } else {
                    const uint32_t krow = (uint32_t)(ks * 16 + 8 * ((lane >> 3) & 1) + (lane & 7));
                    const uint32_t rowo = 24576u + krow * 256u;
#pragma unroll
                    for (int j = 0; j < 2; ++j) {
                        const uint32_t c16 = (uint32_t)((wn >> 3) + (lane >> 4) + (nh * 2 + j) * 2);
                        ldsm4t(bb[j], s0 + rowo + ((c16 ^ (uint32_t)(lane & 7)) << 4));
                    }
                }
#pragma unroll
                for (int mf = 0; mf < 2; ++mf)
#pragma unroll
                    for (int j = 0; j < 2; ++j) {
                        mma16816(C[mf][nh * 4 + j * 2 + 0], aH[mf], &bb[j][0]);
                        mma16816(C[mf][nh * 4 + j * 2 + 1], aH[mf], &bb[j][2]);
                    }
            }
        }
    }

    // ---- epilogue ----------------------------------------------------------
    const int mb = m0 + wm + (lane >> 2);
    const int nbl = wn + 2 * (lane & 3);
#pragma unroll
    for (int mf = 0; mf < 2; ++mf) {
        const size_t r0 = (size_t)(mb + 16 * mf);
#pragma unroll
        for (int nf = 0; nf < 8; ++nf) {
            const int cloc = nbl + nf * 8;
            const int c = n0 + cloc;
            const float b0 = bias_s[cloc], b1 = bias_s[cloc + 1];
            const float v0 = C[mf][nf][0] * alpha + b0;
            const float v1 = C[mf][nf][1] * alpha + b1;
            const float v2 = C[mf][nf][2] * alpha + b0;
            const float v3 = C[mf][nf][3] * alpha + b1;
            if constexpr (MODE == 0) {
                *(float2*)&Cf[r0 * ldC + c]       = make_float2(v0, v1);
                *(float2*)&Cf[(r0 + 8) * ldC + c] = make_float2(v2, v3);
            } else {
                bf16 h0, l0, h1, l1, h2, l2, h3, l3;
                split2(v0, h0, l0); split2(v1, h1, l1);
                split2(v2, h2, l2); split2(v3, h3, l3);
                *(__nv_bfloat162*)&Ch[r0 * ldC + c]       = __nv_bfloat162(h0, h1);
                *(__nv_bfloat162*)&Cl[r0 * ldC + c]       = __nv_bfloat162(l0, l1);
                *(__nv_bfloat162*)&Ch[(r0 + 8) * ldC + c] = __nv_bfloat162(h2, h3);
                *(__nv_bfloat162*)&Cl[(r0 + 8) * ldC + c] = __nv_bfloat162(l2, l3);
            }
        }
    }
}

// ---------------- fp32 -> bf16 hi/lo split ----------------------------------
__global__ void __launch_bounds__(256)
split_kernel(const float* __restrict__ in, bf16* __restrict__ hi,
             bf16* __restrict__ lo, int n4)
{
    const int i = blockIdx.x * 256 + threadIdx.x;
    if (i >= n4) return;
    const float4 x = ((const float4*)in)[i];
    bf16 h0, h1, h2, h3, l0, l1, l2, l3;
    split2(x.x, h0, l0); split2(x.y, h1, l1);
    split2(x.z, h2, l2); split2(x.w, h3, l3);
    ((__nv_bfloat162*)hi)[2 * i]     = __nv_bfloat162(h0, h1);
    ((__nv_bfloat162*)hi)[2 * i + 1] = __nv_bfloat162(h2, h3);
    ((__nv_bfloat162*)lo)[2 * i]     = __nv_bfloat162(l0, l1);
    ((__nv_bfloat162*)lo)[2 * i + 1] = __nv_bfloat162(l2, l3);
}

// ---------------- combine split-K partials (4x) -> bf16 hi/lo ---------------
__global__ void __launch_bounds__(256)
combine_split(const float* __restrict__ part, bf16* __restrict__ hi,
              bf16* __restrict__ lo)
{
    const int i = blockIdx.x * 256 + threadIdx.x;   // float4 index, n4 = 262144
    const float4 a = ((const float4*)part)[i];
    const float4 b = ((const float4*)part)[i + 262144];
    const float4 c = ((const float4*)part)[i + 524288];
    const float4 d = ((const float4*)part)[i + 786432];
    const float4 x = make_float4(a.x + b.x + c.x + d.x, a.y + b.y + c.y + d.y,
                                 a.z + b.z + c.z + d.z, a.w + b.w + c.w + d.w);
    bf16 h0, h1, h2, h3, l0, l1, l2, l3;
    split2(x.x, h0, l0); split2(x.y, h1, l1);
    split2(x.z, h2, l2); split2(x.w, h3, l3);
    ((__nv_bfloat162*)hi)[2 * i]     = __nv_bfloat162(h0, h1);
    ((__nv_bfloat162*)hi)[2 * i + 1] = __nv_bfloat162(h2, h3);
    ((__nv_bfloat162*)lo)[2 * i]     = __nv_bfloat162(l0, l1);
    ((__nv_bfloat162*)lo)[2 * i + 1] = __nv_bfloat162(l2, l3);
}

// ---------------- t[d] = sum_e Wk[e][d] * bq[e]  (W: [3072][1024]) ----------
__global__ void __launch_bounds__(128)
tvec_kernel(const float* __restrict__ W, const float* __restrict__ bvec,
            float* __restrict__ t)
{
    const int d = blockIdx.x * 128 + threadIdx.x;
    float acc = 0.0f;
#pragma unroll 8
    for (int e = 0; e < 3072; ++e) acc += W[(size_t)e * 1024 + d] * bvec[e];
    t[d] = acc;
}

// ---------------- d[i] = sum_e Wo[i][e] * bv[e] + bo[i]  (warp per i) -------
__global__ void __launch_bounds__(256)
dvec_kernel(const float* __restrict__ Wo, const float* __restrict__ bv,
            const float* __restrict__ bo, float* __restrict__ dv)
{
    const int w = (blockIdx.x * 256 + threadIdx.x) >> 5;  // 0..1023
    const int lane = threadIdx.x & 31;
    const float* row = Wo + (size_t)w * 3072;
    float acc = 0.0f;
#pragma unroll
    for (int j = 0; j < 24; ++j) {
        const float4 a = *(const float4*)&row[(lane + j * 32) * 4];
        const float4 b = *(const float4*)&bv[(lane + j * 32) * 4];
        acc += a.x * b.x + a.y * b.y + a.z * b.z + a.w * b.w;
    }
#pragma unroll
    for (int o = 16; o > 0; o >>= 1) acc += __shfl_xor_sync(0xffffffffu, acc, o);
    if (lane == 0) dv[w] = acc + bo[w];
}

// ---------------- b[r] = sum_d X[r][d] * t[d]  (warp per row) ---------------
__global__ void __launch_bounds__(256)
bvec_kernel(const float* __restrict__ X, const float* __restrict__ t,
            float* __restrict__ b)
{
    const int w = (blockIdx.x * 256 + threadIdx.x) >> 5;  // 0..8191
    const int lane = threadIdx.x & 31;
    const float* row = X + (size_t)w * 1024;
    float acc = 0.0f;
#pragma unroll
    for (int j = 0; j < 8; ++j) {
        const float4 a = *(const float4*)&row[(lane + j * 32) * 4];
        const float4 c = *(const float4*)&t[(lane + j * 32) * 4];
        acc += a.x * c.x + a.y * c.y + a.z * c.z + a.w * c.w;
    }
#pragma unroll
    for (int o = 16; o > 0; o >>= 1) acc += __shfl_xor_sync(0xffffffffu, acc, o);
    if (lane == 0) b[w] = acc;
}

// ---------------- softmax over 2048 cols (+0.125*b_m) -> bf16 hi/lo ---------
__global__ void __launch_bounds__(256)
softmax_split(const float* __restrict__ S, const float* __restrict__ bvec,
              bf16* __restrict__ ph, bf16* __restrict__ pl)
{
    const long long row = blockIdx.x;
    const float* p = S + row * 2048;
    const float* bv = bvec + ((row >> 11) << 11);
    const int t = threadIdx.x;

    float4 x0 = *(const float4*)&p[t * 4];
    float4 x1 = *(const float4*)&p[1024 + t * 4];
    const float4 c0 = *(const float4*)&bv[t * 4];
    const float4 c1 = *(const float4*)&bv[1024 + t * 4];
    x0.x += 0.125f * c0.x; x0.y += 0.125f * c0.y;
    x0.z += 0.125f * c0.z; x0.w += 0.125f * c0.w;
    x1.x += 0.125f * c1.x; x1.y += 0.125f * c1.y;
    x1.z += 0.125f * c1.z; x1.w += 0.125f * c1.w;

    float m = fmaxf(fmaxf(fmaxf(x0.x, x0.y), fmaxf(x0.z, x0.w)),
                    fmaxf(fmaxf(x1.x, x1.y), fmaxf(x1.z, x1.w)));
#pragma unroll
    for (int o = 16; o > 0; o >>= 1) m = fmaxf(m, __shfl_xor_sync(0xffffffffu, m, o));
    __shared__ float red[8];
    if ((t & 31) == 0) red[t >> 5] = m;
    __syncthreads();
    m = fmaxf(fmaxf(fmaxf(red[0], red[1]), fmaxf(red[2], red[3])),
              fmaxf(fmaxf(red[4], red[5]), fmaxf(red[6], red[7])));
    __syncthreads();

    float e[8];
    e[0] = __expf(x0.x - m); e[1] = __expf(x0.y - m);
    e[2] = __expf(x0.z - m); e[3] = __expf(x0.w - m);
    e[4] = __expf(x1.x - m); e[5] = __expf(x1.y - m);
    e[6] = __expf(x1.z - m); e[7] = __expf(x1.w - m);

    float s = ((e[0] + e[1]) + (e[2] + e[3])) + ((e[4] + e[5]) + (e[6] + e[7]));
#pragma unroll
    for (int o = 16; o > 0; o >>= 1) s += __shfl_xor_sync(0xffffffffu, s, o);
    if ((t & 31) == 0) red[t >> 5] = s;
    __syncthreads();
    const float inv = 1.0f / (((red[0] + red[1]) + (red[2] + red[3])) +
                              ((red[4] + red[5]) + (red[6] + red[7])));

    bf16* hp = ph + row * 2048;
    bf16* lp = pl + row * 2048;
#pragma unroll
    for (int g = 0; g < 2; ++g) {
        bf16 hh[4], ll[4];
#pragma unroll
        for (int j = 0; j < 4; ++j) split2(e[g * 4 + j] * inv, hh[j], ll[j]);
        const int base = g * 1024 + t * 4;
        *(__nv_bfloat162*)&hp[base]     = __nv_bfloat162(hh[0], hh[1]);
        *(__nv_bfloat162*)&hp[base + 2] = __nv_bfloat162(hh[2], hh[3]);
        *(__nv_bfloat162*)&lp[base]     = __nv_bfloat162(ll[0], ll[1]);
        *(__nv_bfloat162*)&lp[base + 2] = __nv_bfloat162(ll[2], ll[3]);
    }
}

// ---------------------------------------------------------------------------
extern "C" void kernel_launch(void* const* d_in, const int* in_sizes, int n_in,
                              void* d_out, int out_size)
{
    (void)in_sizes; (void)n_in; (void)out_size;
    const float* x  = (const float*)d_in[0];
    const float* Wq = (const float*)d_in[1];
    const float* bq = (const float*)d_in[2];
    const float* Wk = (const float*)d_in[3];
    const float* bk = (const float*)d_in[4];  (void)bk;  // cancels in softmax
    const float* Wv = (const float*)d_in[5];
    const float* bv = (const float*)d_in[6];
    const float* Wo = (const float*)d_in[7];
    const float* bo = (const float*)d_in[8];
    float* out = (float*)d_out;

    bf16 *xh, *xl, *w1h, *w1l, *w2h, *w2l, *mh, *ml, *nh, *nl;
    bf16 *xmh, *xml, *ph, *pl, *c2h, *c2l;
    float *part, *s, *tv, *bvv, *dv;
    cudaGetSymbolAddress((void**)&xh, g_xh);   cudaGetSymbolAddress((void**)&xl, g_xl);
    cudaGetSymbolAddress((void**)&w1h, g_w1h); cudaGetSymbolAddress((void**)&w1l, g_w1l);
    cudaGetSymbolAddress((void**)&w2h, g_w2h); cudaGetSymbolAddress((void**)&w2l, g_w2l);
    cudaGetSymbolAddress((void**)&part, g_part);
    cudaGetSymbolAddress((void**)&mh, g_mh);   cudaGetSymbolAddress((void**)&ml, g_ml);
    cudaGetSymbolAddress((void**)&nh, g_nh);   cudaGetSymbolAddress((void**)&nl, g_nl);
    cudaGetSymbolAddress((void**)&xmh, g_xmh); cudaGetSymbolAddress((void**)&xml, g_xml);
    cudaGetSymbolAddress((void**)&s, g_s);
    cudaGetSymbolAddress((void**)&ph, g_ph);   cudaGetSymbolAddress((void**)&pl, g_pl);
    cudaGetSymbolAddress((void**)&c2h, g_c2h); cudaGetSymbolAddress((void**)&c2l, g_c2l);
    cudaGetSymbolAddress((void**)&tv, g_tvec);
    cudaGetSymbolAddress((void**)&bvv, g_bvec);
    cudaGetSymbolAddress((void**)&dv, g_dvec);

    cudaFuncSetAttribute(mma_gemm<false, false, 0>, cudaFuncAttributeMaxDynamicSharedMemorySize, SMEM_DYN);
    cudaFuncSetAttribute(mma_gemm<false, false, 1>, cudaFuncAttributeMaxDynamicSharedMemorySize, SMEM_DYN);
    cudaFuncSetAttribute(mma_gemm<false, true, 0>,  cudaFuncAttributeMaxDynamicSharedMemorySize, SMEM_DYN);
    cudaFuncSetAttribute(mma_gemm<false, true, 1>,  cudaFuncAttributeMaxDynamicSharedMemorySize, SMEM_DYN);
    cudaFuncSetAttribute(mma_gemm<true, true, 0>,   cudaFuncAttributeMaxDynamicSharedMemorySize, SMEM_DYN);

    const long long QS = 2048LL * 1024, SS = 2048LL * 2048;

    // split X
    split_kernel<<<8192, 256>>>(x, xh, xl, 8192 * 1024 / 4);

    // ---- bias vectors ------------------------------------------------------
    tvec_kernel<<<8, 128>>>(Wk, bq, tv);          // t = Wk^T bq
    bvec_kernel<<<1024, 256>>>(x, tv, bvv);       // b = X t
    dvec_kernel<<<128, 256>>>(Wo, bv, bo, dv);    // d = Wo bv + bo

    // ---- M = Wq^T Wk (split-K=4; A trans, B trans) -------------------------
    split_kernel<<<3072, 256>>>(Wq, w1h, w1l, 3072 * 1024 / 4);
    split_kernel<<<3072, 256>>>(Wk, w2h, w2l, 3072 * 1024 / 4);
    mma_gemm<true, true, 0><<<dim3(8, 8, 4), 256, SMEM_DYN>>>(
        w1h, w1l, 1024, 768LL * 1024, w2h, w2l, 1024, 768LL * 1024,
        part, nullptr, nullptr, 1024, 1024LL * 1024, nullptr, 1.0f, 768);
    combine_split<<<1024, 256>>>(part, mh, ml);

    // ---- N = Wo Wv (split-K=4; A normal, B trans) --------------------------
    split_kernel<<<3072, 256>>>(Wo, w1h, w1l, 1024 * 3072 / 4);
    split_kernel<<<3072, 256>>>(Wv, w2h, w2l, 3072 * 1024 / 4);
    mma_gemm<false, true, 0><<<dim3(8, 8, 4), 256, SMEM_DYN>>>(
        w1h, w1l, 3072, 768, w2h, w2l, 1024, 768LL * 1024,
        part, nullptr, nullptr, 1024, 1024LL * 1024, nullptr, 1.0f, 768);
    combine_split<<<1024, 256>>>(part, nh, nl);

    // ---- XM = X * M  (B = M row-major [k][n] -> TRB) -----------------------
    mma_gemm<false, true, 1><<<dim3(8, 64, 1), 256, SMEM_DYN>>>(
        xh, xl, 1024, 0, mh, ml, 1024, 0,
        nullptr, xmh, xml, 1024, 0, nullptr, 1.0f, 1024);

    // ---- scores = 0.125 * (XM) X^T per batch -------------------------------
    mma_gemm<false, false, 0><<<dim3(16, 16, 4), 256, SMEM_DYN>>>(
        xmh, xml, 1024, QS, xh, xl, 1024, QS,
        s, nullptr, nullptr, 2048, SS, nullptr, 0.125f, 1024);

    // ---- softmax (adds 0.125*b_m) -> split probs ---------------------------
    softmax_split<<<8192, 256>>>(s, bvv, ph, pl);

    // ---- C2 = P X per batch (B = X [k][n] -> TRB) --------------------------
    mma_gemm<false, true, 1><<<dim3(8, 16, 4), 256, SMEM_DYN>>>(
        ph, pl, 2048, SS, xh, xl, 1024, QS,
        nullptr, c2h, c2l, 1024, QS, nullptr, 1.0f, 2048);

    // ---- out = C2 N^T + d --------------------------------------------------
    mma_gemm<false, false, 0><<<dim3(8, 64, 1), 256, SMEM_DYN>>>(
        c2h, c2l, 1024, 0, nh, nl, 1024, 0,
        out, nullptr, nullptr, 1024, 0, dv, 1.0f, 1024);
}

// round 5
// speedup vs baseline: 7.8301x; 1.2465x over previous
#include <cuda_runtime.h>
#include <cuda_bf16.h>
#include <cstdint>

typedef __nv_bfloat16 bf16;

// ---------------- scratch (device globals; allocation is forbidden) --------
__device__ bf16 g_xh[8192 * 1024], g_xl[8192 * 1024];
__device__ bf16 g_w1h[3072 * 1024], g_w1l[3072 * 1024];  // Wq split
__device__ bf16 g_w2h[3072 * 1024], g_w2l[3072 * 1024];  // Wk split
__device__ bf16 g_w3h[3072 * 1024], g_w3l[3072 * 1024];  // Wo split
__device__ bf16 g_w4h[3072 * 1024], g_w4l[3072 * 1024];  // Wv split
__device__ float g_part[8 * 1024 * 1024];                // split-K partials (M:0-3, N:4-7)
__device__ bf16 g_mh[1024 * 1024], g_ml[1024 * 1024];    // M = Wq^T Wk
__device__ bf16 g_nh[1024 * 1024], g_nl[1024 * 1024];    // N = Wo Wv
__device__ bf16 g_xmh[8192 * 1024], g_xml[8192 * 1024];  // X*M
__device__ float g_s[8192 * 2048];                       // scores
__device__ bf16 g_ph[8192 * 2048], g_pl[8192 * 2048];    // probs
__device__ bf16 g_c2h[8192 * 1024], g_c2l[8192 * 1024];  // P*X
__device__ float g_tvec[1024];   // Wk^T bq
__device__ float g_bvec[8192];   // X * tvec
__device__ float g_dvec[1024];   // Wo bv + bo

// ---------------- helpers ---------------------------------------------------
__device__ __forceinline__ uint32_t smem_u32(const void* p) {
    uint32_t a;
    asm("{ .reg .u64 t; cvta.to.shared.u64 t, %1; cvt.u32.u64 %0, t; }"
        : "=r"(a) : "l"(p));
    return a;
}
__device__ __forceinline__ void cp16(uint32_t s, const void* g) {
    asm volatile("cp.async.cg.shared.global [%0], [%1], 16;" :: "r"(s), "l"(g));
}
__device__ __forceinline__ void cp_commit() {
    asm volatile("cp.async.commit_group;" ::: "memory");
}
__device__ __forceinline__ void cp_wait1() {
    asm volatile("cp.async.wait_group 1;" ::: "memory");
}
__device__ __forceinline__ void ldsm4(uint32_t* r, uint32_t a) {
    asm volatile("ldmatrix.sync.aligned.m8n8.x4.shared.b16 {%0,%1,%2,%3}, [%4];"
                 : "=r"(r[0]), "=r"(r[1]), "=r"(r[2]), "=r"(r[3]) : "r"(a));
}
__device__ __forceinline__ void ldsm4t(uint32_t* r, uint32_t a) {
    asm volatile("ldmatrix.sync.aligned.m8n8.x4.trans.shared.b16 {%0,%1,%2,%3}, [%4];"
                 : "=r"(r[0]), "=r"(r[1]), "=r"(r[2]), "=r"(r[3]) : "r"(a));
}
__device__ __forceinline__ void mma16816(float* d, const uint32_t* a, const uint32_t* b) {
    asm volatile("mma.sync.aligned.m16n8k16.row.col.f32.bf16.bf16.f32 "
                 "{%0,%1,%2,%3}, {%4,%5,%6,%7}, {%8,%9}, {%0,%1,%2,%3};"
                 : "+f"(d[0]), "+f"(d[1]), "+f"(d[2]), "+f"(d[3])
                 : "r"(a[0]), "r"(a[1]), "r"(a[2]), "r"(a[3]), "r"(b[0]), "r"(b[1]));
}
__device__ __forceinline__ void split2(float x, bf16& h, bf16& l) {
    h = __float2bfloat16(x);
    l = __float2bfloat16(x - __bfloat162float(h));
}

// ---------------------------------------------------------------------------
// D[m][n] = alpha * sum_k A[m][k] * B^T[n][k]  (+ bias[n])
//   TRA: A given as [k][m] -> ldmatrix.trans for A fragments
//   TRB: B given as [k][n] -> ldmatrix.trans for B fragments
//   MODE=0: write fp32 Cf;  MODE=1: write bf16 hi/lo split Ch/Cl
// CTA 128x128, BK=32, 256 threads, 3-stage cp.async pipeline.
// ---------------------------------------------------------------------------
#define STG_B 32768
#define NSTG  3
#define SMEM_DYN (NSTG * STG_B)

template <bool TRA, bool TRB, int MODE>
__global__ void __launch_bounds__(256, 2)
mma_gemm(const bf16* __restrict__ Ah, const bf16* __restrict__ Al, int ldA, long long sAz,
         const bf16* __restrict__ Bh, const bf16* __restrict__ Bl, int ldB, long long sBz,
         float* __restrict__ Cf, bf16* __restrict__ Ch, bf16* __restrict__ Cl,
         int ldC, long long sCz, const float* __restrict__ bias, float alpha, int K)
{
    extern __shared__ char smem[];
    __shared__ float bias_s[128];
    const uint32_t sb = smem_u32(smem);
    const int tid = threadIdx.x, lane = tid & 31, wid = tid >> 5;
    const int m0 = blockIdx.y * 128, n0 = blockIdx.x * 128;
    const long long z = blockIdx.z;

    Ah += z * sAz; Al += z * sAz;
    Bh += z * sBz; Bl += z * sBz;
    if constexpr (MODE == 0) { Cf += z * sCz; }
    else                     { Ch += z * sCz; Cl += z * sCz; }

    if (tid < 128) bias_s[tid] = bias ? bias[n0 + tid] : 0.0f;

    const size_t ldAs = (size_t)ldA, ldBs = (size_t)ldB;

    // ---- loader precompute ------------------------------------------------
    const int arow = tid >> 2, ac16 = tid & 3;     // NT mapping
    const int krowL = tid >> 4, kc16 = tid & 15;   // trans mapping
    const bf16 *pAh, *pAl;
    uint32_t sAoff;
    if constexpr (!TRA) {
        pAh = Ah + (size_t)(m0 + arow) * ldAs + ac16 * 8;
        pAl = Al + (size_t)(m0 + arow) * ldAs + ac16 * 8;
        sAoff = (uint32_t)arow * 64u + (uint32_t)((ac16 ^ ((arow >> 1) & 3)) << 4);
    } else {
        pAh = Ah + (size_t)krowL * ldAs + m0 + kc16 * 8;
        pAl = Al + (size_t)krowL * ldAs + m0 + kc16 * 8;
        sAoff = (uint32_t)krowL * 256u + (uint32_t)((kc16 ^ (krowL & 7)) << 4);
    }
    const bf16 *pBh, *pBl;
    uint32_t sBoff;
    if constexpr (!TRB) {
        pBh = Bh + (size_t)(n0 + arow) * ldBs + ac16 * 8;
        pBl = Bl + (size_t)(n0 + arow) * ldBs + ac16 * 8;
        sBoff = (uint32_t)arow * 64u + (uint32_t)((ac16 ^ ((arow >> 1) & 3)) << 4);
    } else {
        pBh = Bh + (size_t)krowL * ldBs + n0 + kc16 * 8;
        pBl = Bl + (size_t)krowL * ldBs + n0 + kc16 * 8;
        sBoff = (uint32_t)krowL * 256u + (uint32_t)((kc16 ^ (krowL & 7)) << 4);
    }

    auto load_stage = [&](int slot, int kt) {
        const uint32_t s0 = sb + (uint32_t)slot * STG_B;
        const size_t k0 = (size_t)kt * 32;
#pragma unroll
        for (int i = 0; i < 2; ++i) {
            if constexpr (!TRA) {
                cp16(s0 + i * 4096u + sAoff,         pAh + k0 + (size_t)(i * 64) * ldAs);
                cp16(s0 + 8192u + i * 4096u + sAoff, pAl + k0 + (size_t)(i * 64) * ldAs);
            } else {
                cp16(s0 + i * 4096u + sAoff,         pAh + (k0 + i * 16) * ldAs);
                cp16(s0 + 8192u + i * 4096u + sAoff, pAl + (k0 + i * 16) * ldAs);
            }
        }
#pragma unroll
        for (int i = 0; i < 2; ++i) {
            if constexpr (!TRB) {
                cp16(s0 + 16384u + i * 4096u + sBoff, pBh + k0 + (size_t)(i * 64) * ldBs);
                cp16(s0 + 24576u + i * 4096u + sBoff, pBl + k0 + (size_t)(i * 64) * ldBs);
            } else {
                cp16(s0 + 16384u + i * 4096u + sBoff, pBh + (k0 + i * 16) * ldBs);
                cp16(s0 + 24576u + i * 4096u + sBoff, pBl + (k0 + i * 16) * ldBs);
            }
        }
    };

    // ---- per-warp fragment addressing -------------------------------------
    const int wm = (wid & 3) * 32, wn = (wid >> 2) * 64;
    const int rowAf = wm + (lane & 15);
    const uint32_t swzA = (uint32_t)((rowAf >> 1) & 3);
    const int nrow = wn + (lane & 7) + 8 * (lane >> 4);
    const uint32_t swzB = (uint32_t)((nrow >> 1) & 3);

    float C[2][8][4];
#pragma unroll
    for (int a = 0; a < 2; ++a)
#pragma unroll
        for (int b = 0; b < 8; ++b)
#pragma unroll
            for (int c = 0; c < 4; ++c) C[a][b][c] = 0.0f;

    const int nk = K >> 5;
    load_stage(0, 0); cp_commit();
    load_stage(1, 1); cp_commit();

    for (int kt = 0; kt < nk; ++kt) {
        cp_wait1();
        __syncthreads();
        if (kt + 2 < nk) load_stage((kt + 2) % NSTG, kt + 2);
        cp_commit();

        const uint32_t s0 = sb + (uint32_t)(kt % NSTG) * STG_B;
#pragma unroll
        for (int ks = 0; ks < 2; ++ks) {
            uint32_t aH[2][4], aL[2][4];
            if constexpr (!TRA) {
                const uint32_t kcA = (uint32_t)(ks * 2 + (lane >> 4));
#pragma unroll
                for (int mf = 0; mf < 2; ++mf) {
                    const uint32_t off = (uint32_t)(rowAf + 16 * mf) * 64u + ((kcA ^ swzA) << 4);
                    ldsm4(aH[mf], s0 + off);
                    ldsm4(aL[mf], s0 + 8192u + off);
                }
            } else {
                const uint32_t krow = (uint32_t)(ks * 16 + 8 * (lane >> 4) + (lane & 7));
                const uint32_t rowo = krow * 256u;
#pragma unroll
                for (int mf = 0; mf < 2; ++mf) {
                    const uint32_t c16 = (uint32_t)((wm >> 3) + 2 * mf + ((lane >> 3) & 1));
                    const uint32_t off = rowo + ((c16 ^ (uint32_t)(lane & 7)) << 4);
                    ldsm4t(aH[mf], s0 + off);
                    ldsm4t(aL[mf], s0 + 8192u + off);
                }
            }

#pragma unroll
            for (int nh = 0; nh < 2; ++nh) {
                uint32_t bb[2][4];
                // ---- Bh fragments: terms Ah*Bh + Al*Bh ----
                if constexpr (!TRB) {
                    const uint32_t kcB = (uint32_t)(ks * 2 + ((lane >> 3) & 1));
#pragma unroll
                    for (int j = 0; j < 2; ++j) {
                        const int nf2 = nh * 2 + j;
                        const uint32_t off = 16384u + (uint32_t)(nrow + 16 * nf2) * 64u +
                                             ((kcB ^ swzB) << 4);
                        ldsm4(bb[j], s0 + off);
                    }
                } else {
                    const uint32_t krow = (uint32_t)(ks * 16 + 8 * ((lane >> 3) & 1) + (lane & 7));
                    const uint32_t rowo = 16384u + krow * 256u;
#pragma unroll
                    for (int j = 0; j < 2; ++j) {
                        const uint32_t c16 = (uint32_t)((wn >> 3) + (lane >> 4) + (nh * 2 + j) * 2);
                        ldsm4t(bb[j], s0 + rowo + ((c16 ^ (uint32_t)(lane & 7)) << 4));
                    }
                }
#pragma unroll
                for (int mf = 0; mf < 2; ++mf)
#pragma unroll
                    for (int j = 0; j < 2; ++j) {
                        mma16816(C[mf][nh * 4 + j * 2 + 0], aH[mf], &bb[j][0]);
                        mma16816(C[mf][nh * 4 + j * 2 + 1], aH[mf], &bb[j][2]);
                    }
#pragma unroll
                for (int mf = 0; mf < 2; ++mf)
#pragma unroll
                    for (int j = 0; j < 2; ++j) {
                        mma16816(C[mf][nh * 4 + j * 2 + 0], aL[mf], &bb[j][0]);
                        mma16816(C[mf][nh * 4 + j * 2 + 1], aL[mf], &bb[j][2]);
                    }
                // ---- Bl fragments: term Ah*Bl ----
                if constexpr (!TRB) {
                    const uint32_t kcB = (uint32_t)(ks * 2 + ((lane >> 3) & 1));
#pragma unroll
                    for (int j = 0; j < 2; ++j) {
                        const int nf2 = nh * 2 + j;
                        const uint32_t off = 24576u + (uint32_t)(nrow + 16 * nf2) * 64u +
                                             ((kcB ^ swzB) << 4);
                        ldsm4(bb[j], s0 + off);
                    }
                } else {
                    const uint32_t krow = (uint32_t)(ks * 16 + 8 * ((lane >> 3) & 1) + (lane & 7));
                    const uint32_t rowo = 24576u + krow * 256u;
#pragma unroll
                    for (int j = 0; j < 2; ++j) {
                        const uint32_t c16 = (uint32_t)((wn >> 3) + (lane >> 4) + (nh * 2 + j) * 2);
                        ldsm4t(bb[j], s0 + rowo + ((c16 ^ (uint32_t)(lane & 7)) << 4));
                    }
                }
#pragma unroll
                for (int mf = 0; mf < 2; ++mf)
#pragma unroll
                    for (int j = 0; j < 2; ++j) {
                        mma16816(C[mf][nh * 4 + j * 2 + 0], aH[mf], &bb[j][0]);
                        mma16816(C[mf][nh * 4 + j * 2 + 1], aH[mf], &bb[j][2]);
                    }
            }
        }
    }

    // ---- epilogue ----------------------------------------------------------
    const int mb = m0 + wm + (lane >> 2);
    const int nbl = wn + 2 * (lane & 3);
#pragma unroll
    for (int mf = 0; mf < 2; ++mf) {
        const size_t r0 = (size_t)(mb + 16 * mf);
#pragma unroll
        for (int nf = 0; nf < 8; ++nf) {
            const int cloc = nbl + nf * 8;
            const int c = n0 + cloc;
            const float b0 = bias_s[cloc], b1 = bias_s[cloc + 1];
            const float v0 = C[mf][nf][0] * alpha + b0;
            const float v1 = C[mf][nf][1] * alpha + b1;
            const float v2 = C[mf][nf][2] * alpha + b0;
            const float v3 = C[mf][nf][3] * alpha + b1;
            if constexpr (MODE == 0) {
                *(float2*)&Cf[r0 * ldC + c]       = make_float2(v0, v1);
                *(float2*)&Cf[(r0 + 8) * ldC + c] = make_float2(v2, v3);
            } else {
                bf16 h0, l0, h1, l1, h2, l2, h3, l3;
                split2(v0, h0, l0); split2(v1, h1, l1);
                split2(v2, h2, l2); split2(v3, h3, l3);
                *(__nv_bfloat162*)&Ch[r0 * ldC + c]       = __nv_bfloat162(h0, h1);
                *(__nv_bfloat162*)&Cl[r0 * ldC + c]       = __nv_bfloat162(l0, l1);
                *(__nv_bfloat162*)&Ch[(r0 + 8) * ldC + c] = __nv_bfloat162(h2, h3);
                *(__nv_bfloat162*)&Cl[(r0 + 8) * ldC + c] = __nv_bfloat162(l2, l3);
            }
        }
    }
}

// ---------------------------------------------------------------------------
// prep: fused splits (X, Wq, Wk, Wo, Wv) + tvec partials + dvec partials
// blocks: [0,8192) X | [8192,11264) Wq | [11264,14336) Wk |
//         [14336,17408) Wo | [17408,20480) Wv | [20480,20672) tvec | rest dvec
// ---------------------------------------------------------------------------
__global__ void __launch_bounds__(256)
prep_kernel(const float* __restrict__ x,  const float* __restrict__ Wq,
            const float* __restrict__ Wk, const float* __restrict__ Wv,
            const float* __restrict__ Wo, const float* __restrict__ bq,
            const float* __restrict__ bv,
            bf16* __restrict__ xh,  bf16* __restrict__ xl,
            bf16* __restrict__ w1h, bf16* __restrict__ w1l,
            bf16* __restrict__ w2h, bf16* __restrict__ w2l,
            bf16* __restrict__ w3h, bf16* __restrict__ w3l,
            bf16* __restrict__ w4h, bf16* __restrict__ w4l,
            float* __restrict__ tpart, float* __restrict__ dpart)
{
    __shared__ float sred[256];
    const int b = blockIdx.x;
    const int tid = threadIdx.x;

    if (b < 20480) {
        const float* src; bf16 *dh, *dl; int i0;
        if (b < 8192)       { src = x;  dh = xh;  dl = xl;  i0 = b; }
        else if (b < 11264) { src = Wq; dh = w1h; dl = w1l; i0 = b - 8192; }
        else if (b < 14336) { src = Wk; dh = w2h; dl = w2l; i0 = b - 11264; }
        else if (b < 17408) { src = Wo; dh = w3h; dl = w3l; i0 = b - 14336; }
        else                { src = Wv; dh = w4h; dl = w4l; i0 = b - 17408; }
        const int i = i0 * 256 + tid;
        const float4 v = ((const float4*)src)[i];
        bf16 h0, h1, h2, h3, l0, l1, l2, l3;
        split2(v.x, h0, l0); split2(v.y, h1, l1);
        split2(v.z, h2, l2); split2(v.w, h3, l3);
        ((__nv_bfloat162*)dh)[2 * i]     = __nv_bfloat162(h0, h1);
        ((__nv_bfloat162*)dh)[2 * i + 1] = __nv_bfloat162(h2, h3);
        ((__nv_bfloat162*)dl)[2 * i]     = __nv_bfloat162(l0, l1);
        ((__nv_bfloat162*)dl)[2 * i + 1] = __nv_bfloat162(l2, l3);
    } else if (b < 20672) {
        // tvec partials: tpart[ec][d] = sum_{e in chunk ec} Wk[e][d] * bq[e]
        const int t = b - 20480;          // 0..191
        const int ec = t / 8, dc = t % 8; // 24 e-chunks x 8 d-chunks
        const int d = dc * 128 + (tid & 127);
        const int el = tid >> 7;          // 0 or 1
        float acc = 0.0f;
#pragma unroll 8
        for (int j = 0; j < 64; ++j) {
            const int e = ec * 128 + el * 64 + j;
            acc += Wk[(size_t)e * 1024 + d] * bq[e];
        }
        sred[tid] = acc;
        __syncthreads();
        if (tid < 128) tpart[ec * 1024 + d] = sred[tid] + sred[tid + 128];
    } else {
        // dvec partials: dpart[ch][row] = sum_{e in chunk ch} Wo[row][e]*bv[e]
        const int fw = (b - 20672) * 8 + (tid >> 5);  // flat warp 0..24575
        const int row = fw / 24, ch = fw % 24;
        const int lane = tid & 31;
        const float4 a = *(const float4*)&Wo[(size_t)row * 3072 + ch * 128 + lane * 4];
        const float4 c = *(const float4*)&bv[ch * 128 + lane * 4];
        float acc = a.x * c.x + a.y * c.y + a.z * c.z + a.w * c.w;
#pragma unroll
        for (int o = 16; o > 0; o >>= 1) acc += __shfl_xor_sync(0xffffffffu, acc, o);
        if (lane == 0) dpart[ch * 1024 + row] = acc;
    }
}

// ---------------- reduce tvec/dvec partials ---------------------------------
__global__ void __launch_bounds__(256)
vec_reduce(const float* __restrict__ tpart, const float* __restrict__ dpart,
           const float* __restrict__ bo, float* __restrict__ t, float* __restrict__ dv)
{
    const int i = blockIdx.x * 256 + threadIdx.x;  // 0..2047
    if (i < 1024) {
        float a = 0.0f;
#pragma unroll
        for (int e = 0; e < 24; ++e) a += tpart[e * 1024 + i];
        t[i] = a;
    } else {
        const int j = i - 1024;
        float a = 0.0f;
#pragma unroll
        for (int e = 0; e < 24; ++e) a += dpart[e * 1024 + j];
        dv[j] = a + bo[j];
    }
}

// ---------------- combine split-K partials for BOTH M and N ------------------
__global__ void __launch_bounds__(256)
combine2(const float* __restrict__ part, bf16* __restrict__ mh, bf16* __restrict__ ml,
         bf16* __restrict__ nh, bf16* __restrict__ nl)
{
    const int bb = blockIdx.x;                     // 0..2047
    const int half = bb >> 10;                     // 0 = M, 1 = N
    const int i = (bb & 1023) * 256 + threadIdx.x; // float4 index, 262144 per matrix
    const float* p = part + (size_t)half * 4194304;
    const float4 a = ((const float4*)p)[i];
    const float4 b = ((const float4*)p)[i + 262144];
    const float4 c = ((const float4*)p)[i + 524288];
    const float4 d = ((const float4*)p)[i + 786432];
    const float4 x = make_float4(a.x + b.x + c.x + d.x, a.y + b.y + c.y + d.y,
                                 a.z + b.z + c.z + d.z, a.w + b.w + c.w + d.w);
    bf16* hi = half ? nh : mh;
    bf16* lo = half ? nl : ml;
    bf16 h0, h1, h2, h3, l0, l1, l2, l3;
    split2(x.x, h0, l0); split2(x.y, h1, l1);
    split2(x.z, h2, l2); split2(x.w, h3, l3);
    ((__nv_bfloat162*)hi)[2 * i]     = __nv_bfloat162(h0, h1);
    ((__nv_bfloat162*)hi)[2 * i + 1] = __nv_bfloat162(h2, h3);
    ((__nv_bfloat162*)lo)[2 * i]     = __nv_bfloat162(l0, l1);
    ((__nv_bfloat162*)lo)[2 * i + 1] = __nv_bfloat162(l2, l3);
}

// ---------------- b[r] = sum_d X[r][d] * t[d]  (warp per row) ---------------
__global__ void __launch_bounds__(256)
bvec_kernel(const float* __restrict__ X, const float* __restrict__ t,
            float* __restrict__ b)
{
    const int w = (blockIdx.x * 256 + threadIdx.x) >> 5;  // 0..8191
    const int lane = threadIdx.x & 31;
    const float* row = X + (size_t)w * 1024;
    float acc = 0.0f;
#pragma unroll
    for (int j = 0; j < 8; ++j) {
        const float4 a = *(const float4*)&row[(lane + j * 32) * 4];
        const float4 c = *(const float4*)&t[(lane + j * 32) * 4];
        acc += a.x * c.x + a.y * c.y + a.z * c.z + a.w * c.w;
    }
#pragma unroll
    for (int o = 16; o > 0; o >>= 1) acc += __shfl_xor_sync(0xffffffffu, acc, o);
    if (lane == 0) b[w] = acc;
}

// ---------------- softmax over 2048 cols (+0.125*b_m) -> bf16 hi/lo ---------
__global__ void __launch_bounds__(256)
softmax_split(const float* __restrict__ S, const float* __restrict__ bvec,
              bf16* __restrict__ ph, bf16* __restrict__ pl)
{
    const long long row = blockIdx.x;
    const float* p = S + row * 2048;
    const float* bv = bvec + ((row >> 11) << 11);
    const int t = threadIdx.x;

    float4 x0 = *(const float4*)&p[t * 4];
    float4 x1 = *(const float4*)&p[1024 + t * 4];
    const float4 c0 = *(const float4*)&bv[t * 4];
    const float4 c1 = *(const float4*)&bv[1024 + t * 4];
    x0.x += 0.125f * c0.x; x0.y += 0.125f * c0.y;
    x0.z += 0.125f * c0.z; x0.w += 0.125f * c0.w;
    x1.x += 0.125f * c1.x; x1.y += 0.125f * c1.y;
    x1.z += 0.125f * c1.z; x1.w += 0.125f * c1.w;

    float m = fmaxf(fmaxf(fmaxf(x0.x, x0.y), fmaxf(x0.z, x0.w)),
                    fmaxf(fmaxf(x1.x, x1.y), fmaxf(x1.z, x1.w)));
#pragma unroll
    for (int o = 16; o > 0; o >>= 1) m = fmaxf(m, __shfl_xor_sync(0xffffffffu, m, o));
    __shared__ float red[8];
    if ((t & 31) == 0) red[t >> 5] = m;
    __syncthreads();
    m = fmaxf(fmaxf(fmaxf(red[0], red[1]), fmaxf(red[2], red[3])),
              fmaxf(fmaxf(red[4], red[5]), fmaxf(red[6], red[7])));
    __syncthreads();

    float e[8];
    e[0] = __expf(x0.x - m); e[1] = __expf(x0.y - m);
    e[2] = __expf(x0.z - m); e[3] = __expf(x0.w - m);
    e[4] = __expf(x1.x - m); e[5] = __expf(x1.y - m);
    e[6] = __expf(x1.z - m); e[7] = __expf(x1.w - m);

    float s = ((e[0] + e[1]) + (e[2] + e[3])) + ((e[4] + e[5]) + (e[6] + e[7]));
#pragma unroll
    for (int o = 16; o > 0; o >>= 1) s += __shfl_xor_sync(0xffffffffu, s, o);
    if ((t & 31) == 0) red[t >> 5] = s;
    __syncthreads();
    const float inv = 1.0f / (((red[0] + red[1]) + (red[2] + red[3])) +
                              ((red[4] + red[5]) + (red[6] + red[7])));

    bf16* hp = ph + row * 2048;
    bf16* lp = pl + row * 2048;
#pragma unroll
    for (int g = 0; g < 2; ++g) {
        bf16 hh[4], ll[4];
#pragma unroll
        for (int j = 0; j < 4; ++j) split2(e[g * 4 + j] * inv, hh[j], ll[j]);
        const int base = g * 1024 + t * 4;
        *(__nv_bfloat162*)&hp[base]     = __nv_bfloat162(hh[0], hh[1]);
        *(__nv_bfloat162*)&hp[base + 2] = __nv_bfloat162(hh[2], hh[3]);
        *(__nv_bfloat162*)&lp[base]     = __nv_bfloat162(ll[0], ll[1]);
        *(__nv_bfloat162*)&lp[base + 2] = __nv_bfloat162(ll[2], ll[3]);
    }
}

// ---------------------------------------------------------------------------
extern "C" void kernel_launch(void* const* d_in, const int* in_sizes, int n_in,
                              void* d_out, int out_size)
{
    (void)in_sizes; (void)n_in; (void)out_size;
    const float* x  = (const float*)d_in[0];
    const float* Wq = (const float*)d_in[1];
    const float* bq = (const float*)d_in[2];
    const float* Wk = (const float*)d_in[3];
    const float* bk = (const float*)d_in[4];  (void)bk;  // cancels in softmax
    const float* Wv = (const float*)d_in[5];
    const float* bv = (const float*)d_in[6];
    const float* Wo = (const float*)d_in[7];
    const float* bo = (const float*)d_in[8];
    float* out = (float*)d_out;

    bf16 *xh, *xl, *w1h, *w1l, *w2h, *w2l, *w3h, *w3l, *w4h, *w4l;
    bf16 *mh, *ml, *nh, *nl, *xmh, *xml, *ph, *pl, *c2h, *c2l;
    float *part, *s, *tv, *bvv, *dv;
    cudaGetSymbolAddress((void**)&xh, g_xh);   cudaGetSymbolAddress((void**)&xl, g_xl);
    cudaGetSymbolAddress((void**)&w1h, g_w1h); cudaGetSymbolAddress((void**)&w1l, g_w1l);
    cudaGetSymbolAddress((void**)&w2h, g_w2h); cudaGetSymbolAddress((void**)&w2l, g_w2l);
    cudaGetSymbolAddress((void**)&w3h, g_w3h); cudaGetSymbolAddress((void**)&w3l, g_w3l);
    cudaGetSymbolAddress((void**)&w4h, g_w4h); cudaGetSymbolAddress((void**)&w4l, g_w4l);
    cudaGetSymbolAddress((void**)&part, g_part);
    cudaGetSymbolAddress((void**)&mh, g_mh);   cudaGetSymbolAddress((void**)&ml, g_ml);
    cudaGetSymbolAddress((void**)&nh, g_nh);   cudaGetSymbolAddress((void**)&nl, g_nl);
    cudaGetSymbolAddress((void**)&xmh, g_xmh); cudaGetSymbolAddress((void**)&xml, g_xml);
    cudaGetSymbolAddress((void**)&s, g_s);
    cudaGetSymbolAddress((void**)&ph, g_ph);   cudaGetSymbolAddress((void**)&pl, g_pl);
    cudaGetSymbolAddress((void**)&c2h, g_c2h); cudaGetSymbolAddress((void**)&c2l, g_c2l);
    cudaGetSymbolAddress((void**)&tv, g_tvec);
    cudaGetSymbolAddress((void**)&bvv, g_bvec);
    cudaGetSymbolAddress((void**)&dv, g_dvec);

    cudaFuncSetAttribute(mma_gemm<false, false, 0>, cudaFuncAttributeMaxDynamicSharedMemorySize, SMEM_DYN);
    cudaFuncSetAttribute(mma_gemm<false, true, 0>,  cudaFuncAttributeMaxDynamicSharedMemorySize, SMEM_DYN);
    cudaFuncSetAttribute(mma_gemm<false, true, 1>,  cudaFuncAttributeMaxDynamicSharedMemorySize, SMEM_DYN);
    cudaFuncSetAttribute(mma_gemm<true, true, 0>,   cudaFuncAttributeMaxDynamicSharedMemorySize, SMEM_DYN);

    const long long QS = 2048LL * 1024, SS = 2048LL * 2048;

    // ---- fused prep: all splits + tvec/dvec partials -----------------------
    // tpart = part[0:24576), dpart = part[32768:57344) — consumed by
    // vec_reduce BEFORE the M/N GEMMs overwrite part.
    prep_kernel<<<23744, 256>>>(x, Wq, Wk, Wv, Wo, bq, bv,
                                xh, xl, w1h, w1l, w2h, w2l, w3h, w3l, w4h, w4l,
                                part, part + 32768);
    vec_reduce<<<8, 256>>>(part, part + 32768, bo, tv, dv);
    bvec_kernel<<<1024, 256>>>(x, tv, bvv);   // b = X t

    // ---- M = Wq^T Wk (split-K=4 -> slabs 0-3) ------------------------------
    mma_gemm<true, true, 0><<<dim3(8, 8, 4), 256, SMEM_DYN>>>(
        w1h, w1l, 1024, 768LL * 1024, w2h, w2l, 1024, 768LL * 1024,
        part, nullptr, nullptr, 1024, 1024LL * 1024, nullptr, 1.0f, 768);

    // ---- N = Wo Wv (split-K=4 -> slabs 4-7) --------------------------------
    mma_gemm<false, true, 0><<<dim3(8, 8, 4), 256, SMEM_DYN>>>(
        w3h, w3l, 3072, 768, w4h, w4l, 1024, 768LL * 1024,
        part + 4LL * 1024 * 1024, nullptr, nullptr, 1024, 1024LL * 1024,
        nullptr, 1.0f, 768);

    // ---- combine both ------------------------------------------------------
    combine2<<<2048, 256>>>(part, mh, ml, nh, nl);

    // ---- XM = X * M  (B = M row-major [k][n] -> TRB) -----------------------
    mma_gemm<false, true, 1><<<dim3(8, 64, 1), 256, SMEM_DYN>>>(
        xh, xl, 1024, 0, mh, ml, 1024, 0,
        nullptr, xmh, xml, 1024, 0, nullptr, 1.0f, 1024);

    // ---- scores = 0.125 * (XM) X^T per batch -------------------------------
    mma_gemm<false, false, 0><<<dim3(16, 16, 4), 256, SMEM_DYN>>>(
        xmh, xml, 1024, QS, xh, xl, 1024, QS,
        s, nullptr, nullptr, 2048, SS, nullptr, 0.125f, 1024);

    // ---- softmax (adds 0.125*b_m) -> split probs ---------------------------
    softmax_split<<<8192, 256>>>(s, bvv, ph, pl);

    // ---- C2 = P X per batch (B = X [k][n] -> TRB) --------------------------
    mma_gemm<false, true, 1><<<dim3(8, 16, 4), 256, SMEM_DYN>>>(
        ph, pl, 2048, SS, xh, xl, 1024, QS,
        nullptr, c2h, c2l, 1024, QS, nullptr, 1.0f, 2048);

    // ---- out = C2 N^T + d --------------------------------------------------
    mma_gemm<false, false, 0><<<dim3(8, 64, 1), 256, SMEM_DYN>>>(
        c2h, c2l, 1024, 0, nh, nl, 1024, 0,
        out, nullptr, nullptr, 1024, 0, dv, 1.0f, 1024);
}

// round 7
// speedup vs baseline: 7.8921x; 1.0079x over previous
#include <cuda_runtime.h>
#include <cuda_bf16.h>
#include <cstdint>

typedef __nv_bfloat16 bf16;

// ---------------- scratch (device globals; allocation is forbidden) --------
__device__ bf16 g_xh[8192 * 1024], g_xl[8192 * 1024];
__device__ bf16 g_w1h[3072 * 1024], g_w1l[3072 * 1024];  // Wq split
__device__ bf16 g_w2h[3072 * 1024], g_w2l[3072 * 1024];  // Wk split
__device__ bf16 g_w3h[3072 * 1024], g_w3l[3072 * 1024];  // Wo split
__device__ bf16 g_w4h[3072 * 1024], g_w4l[3072 * 1024];  // Wv split
__device__ float g_part[16 * 1024 * 1024];               // split-K partials (M:0-7, N:8-15)
__device__ bf16 g_mh[1024 * 1024], g_ml[1024 * 1024];    // M = Wq^T Wk
__device__ bf16 g_nh[1024 * 1024], g_nl[1024 * 1024];    // N = Wo Wv
__device__ bf16 g_xmh[8192 * 1024], g_xml[8192 * 1024];  // X*M
__device__ float g_s[8192 * 2048];                       // scores
__device__ bf16 g_ph[8192 * 2048], g_pl[8192 * 2048];    // probs
__device__ bf16 g_c2h[8192 * 1024], g_c2l[8192 * 1024];  // P*X
__device__ float g_tvec[1024];   // Wk^T bq
__device__ float g_bvec[8192];   // X * tvec
__device__ float g_dvec[1024];   // Wo bv + bo

// ---------------- helpers ---------------------------------------------------
__device__ __forceinline__ uint32_t smem_u32(const void* p) {
    uint32_t a;
    asm("{ .reg .u64 t; cvta.to.shared.u64 t, %1; cvt.u32.u64 %0, t; }"
        : "=r"(a) : "l"(p));
    return a;
}
__device__ __forceinline__ void cp16(uint32_t s, const void* g) {
    asm volatile("cp.async.cg.shared.global [%0], [%1], 16;" :: "r"(s), "l"(g));
}
__device__ __forceinline__ void cp_commit() {
    asm volatile("cp.async.commit_group;" ::: "memory");
}
__device__ __forceinline__ void cp_wait1() {
    asm volatile("cp.async.wait_group 1;" ::: "memory");
}
__device__ __forceinline__ void ldsm4(uint32_t* r, uint32_t a) {
    asm volatile("ldmatrix.sync.aligned.m8n8.x4.shared.b16 {%0,%1,%2,%3}, [%4];"
                 : "=r"(r[0]), "=r"(r[1]), "=r"(r[2]), "=r"(r[3]) : "r"(a));
}
__device__ __forceinline__ void ldsm4t(uint32_t* r, uint32_t a) {
    asm volatile("ldmatrix.sync.aligned.m8n8.x4.trans.shared.b16 {%0,%1,%2,%3}, [%4];"
                 : "=r"(r[0]), "=r"(r[1]), "=r"(r[2]), "=r"(r[3]) : "r"(a));
}
__device__ __forceinline__ void mma16816(float* d, const uint32_t* a, const uint32_t* b) {
    asm volatile("mma.sync.aligned.m16n8k16.row.col.f32.bf16.bf16.f32 "
                 "{%0,%1,%2,%3}, {%4,%5,%6,%7}, {%8,%9}, {%0,%1,%2,%3};"
                 : "+f"(d[0]), "+f"(d[1]), "+f"(d[2]), "+f"(d[3])
                 : "r"(a[0]), "r"(a[1]), "r"(a[2]), "r"(a[3]), "r"(b[0]), "r"(b[1]));
}
__device__ __forceinline__ void split2(float x, bf16& h, bf16& l) {
    h = __float2bfloat16(x);
    l = __float2bfloat16(x - __bfloat162float(h));
}
// FMA-pipe exp (avoids MUFU.EX2 throughput wall). rel err ~3.5e-7 on f in [-.5,.5]
__device__ __forceinline__ float fexp(float x) {
    x = fmaxf(x, -87.0f);
    const float t = x * 1.442695041f;
    const float i = rintf(t);
    const float f = t - i;
    float p = 1.54035e-4f;
    p = fmaf(p, f, 1.333356e-3f);
    p = fmaf(p, f, 9.618129e-3f);
    p = fmaf(p, f, 5.550410e-2f);
    p = fmaf(p, f, 2.402265e-1f);
    p = fmaf(p, f, 6.931472e-1f);
    p = fmaf(p, f, 1.0f);
    return __int_as_float(__float_as_int(p) + ((int)i << 23));
}

// ---------------------------------------------------------------------------
// D[m][n] = alpha * sum_k A[m][k] * B^T[n][k]  (+ bias[n])
//   TRA: A given as [k][m] -> ldmatrix.trans ; TRB: B given as [k][n]
//   MODE=0: write fp32 Cf;  MODE=1: write bf16 hi/lo split Ch/Cl
// CTA 128x128, BK=32, 256 threads, 3-stage cp.async pipeline.
// ---------------------------------------------------------------------------
#define STG_B 32768
#define NSTG  3
#define SMEM_DYN (NSTG * STG_B)

template <bool TRA, bool TRB, int MODE>
__device__ __forceinline__ void gemm_body(
    const bf16* __restrict__ Ah, const bf16* __restrict__ Al, int ldA,
    const bf16* __restrict__ Bh, const bf16* __restrict__ Bl, int ldB,
    float* __restrict__ Cf, bf16* __restrict__ Ch, bf16* __restrict__ Cl,
    int ldC, const float* __restrict__ bias, float alpha, int K, char* smem)
{
    __shared__ float bias_s[128];
    const uint32_t sb = smem_u32(smem);
    const int tid = threadIdx.x, lane = tid & 31, wid = tid >> 5;
    const int m0 = blockIdx.y * 128, n0 = blockIdx.x * 128;

    if (tid < 128) bias_s[tid] = bias ? bias[n0 + tid] : 0.0f;

    const size_t ldAs = (size_t)ldA, ldBs = (size_t)ldB;

    // ---- loader precompute ------------------------------------------------
    const int arow = tid >> 2, ac16 = tid & 3;     // NT mapping
    const int krowL = tid >> 4, kc16 = tid & 15;   // trans mapping
    const bf16 *pAh, *pAl;
    uint32_t sAoff;
    if constexpr (!TRA) {
        pAh = Ah + (size_t)(m0 + arow) * ldAs + ac16 * 8;
        pAl = Al + (size_t)(m0 + arow) * ldAs + ac16 * 8;
        sAoff = (uint32_t)arow * 64u + (uint32_t)((ac16 ^ ((arow >> 1) & 3)) << 4);
    } else {
        pAh = Ah + (size_t)krowL * ldAs + m0 + kc16 * 8;
        pAl = Al + (size_t)krowL * ldAs + m0 + kc16 * 8;
        sAoff = (uint32_t)krowL * 256u + (uint32_t)((kc16 ^ (krowL & 7)) << 4);
    }
    const bf16 *pBh, *pBl;
    uint32_t sBoff;
    if constexpr (!TRB) {
        pBh = Bh + (size_t)(n0 + arow) * ldBs + ac16 * 8;
        pBl = Bl + (size_t)(n0 + arow) * ldBs + ac16 * 8;
        sBoff = (uint32_t)arow * 64u + (uint32_t)((ac16 ^ ((arow >> 1) & 3)) << 4);
    } else {
        pBh = Bh + (size_t)krowL * ldBs + n0 + kc16 * 8;
        pBl = Bl + (size_t)krowL * ldBs + n0 + kc16 * 8;
        sBoff = (uint32_t)krowL * 256u + (uint32_t)((kc16 ^ (krowL & 7)) << 4);
    }

    auto load_stage = [&](int slot, int kt) {
        const uint32_t s0 = sb + (uint32_t)slot * STG_B;
        const size_t k0 = (size_t)kt * 32;
#pragma unroll
        for (int i = 0; i < 2; ++i) {
            if constexpr (!TRA) {
                cp16(s0 + i * 4096u + sAoff,         pAh + k0 + (size_t)(i * 64) * ldAs);
                cp16(s0 + 8192u + i * 4096u + sAoff, pAl + k0 + (size_t)(i * 64) * ldAs);
            } else {
                cp16(s0 + i * 4096u + sAoff,         pAh + (k0 + i * 16) * ldAs);
                cp16(s0 + 8192u + i * 4096u + sAoff, pAl + (k0 + i * 16) * ldAs);
            }
        }
#pragma unroll
        for (int i = 0; i < 2; ++i) {
            if constexpr (!TRB) {
                cp16(s0 + 16384u + i * 4096u + sBoff, pBh + k0 + (size_t)(i * 64) * ldBs);
                cp16(s0 + 24576u + i * 4096u + sBoff, pBl + k0 + (size_t)(i * 64) * ldBs);
            } else {
                cp16(s0 + 16384u + i * 4096u + sBoff, pBh + (k0 + i * 16) * ldBs);
                cp16(s0 + 24576u + i * 4096u + sBoff, pBl + (k0 + i * 16) * ldBs);
            }
        }
    };

    // ---- per-warp fragment addressing -------------------------------------
    const int wm = (wid & 3) * 32, wn = (wid >> 2) * 64;
    const int rowAf = wm + (lane & 15);
    const uint32_t swzA = (uint32_t)((rowAf >> 1) & 3);
    const int nrow = wn + (lane & 7) + 8 * (lane >> 4);
    const uint32_t swzB = (uint32_t)((nrow >> 1) & 3);

    float C[2][8][4];
#pragma unroll
    for (int a = 0; a < 2; ++a)
#pragma unroll
        for (int b = 0; b < 8; ++b)
#pragma unroll
            for (int c = 0; c < 4; ++c) C[a][b][c] = 0.0f;

    const int nk = K >> 5;
    load_stage(0, 0); cp_commit();
    load_stage(1, 1); cp_commit();

    for (int kt = 0; kt < nk; ++kt) {
        cp_wait1();
        __syncthreads();
        if (kt + 2 < nk) load_stage((kt + 2) % NSTG, kt + 2);
        cp_commit();

        const uint32_t s0 = sb + (uint32_t)(kt % NSTG) * STG_B;
#pragma unroll
        for (int ks = 0; ks < 2; ++ks) {
            uint32_t aH[2][4], aL[2][4];
            if constexpr (!TRA) {
                const uint32_t kcA = (uint32_t)(ks * 2 + (lane >> 4));
#pragma unroll
                for (int mf = 0; mf < 2; ++mf) {
                    const uint32_t off = (uint32_t)(rowAf + 16 * mf) * 64u + ((kcA ^ swzA) << 4);
                    ldsm4(aH[mf], s0 + off);
                    ldsm4(aL[mf], s0 + 8192u + off);
                }
            } else {
                const uint32_t krow = (uint32_t)(ks * 16 + 8 * (lane >> 4) + (lane & 7));
                const uint32_t rowo = krow * 256u;
#pragma unroll
                for (int mf = 0; mf < 2; ++mf) {
                    const uint32_t c16 = (uint32_t)((wm >> 3) + 2 * mf + ((lane >> 3) & 1));
                    const uint32_t off = rowo + ((c16 ^ (uint32_t)(lane & 7)) << 4);
                    ldsm4t(aH[mf], s0 + off);
                    ldsm4t(aL[mf], s0 + 8192u + off);
                }
            }

#pragma unroll
            for (int nh = 0; nh < 2; ++nh) {
                uint32_t bb[2][4];
                // ---- Bh fragments: terms Ah*Bh + Al*Bh ----
                if constexpr (!TRB) {
                    const uint32_t kcB = (uint32_t)(ks * 2 + ((lane >> 3) & 1));
#pragma unroll
                    for (int j = 0; j < 2; ++j) {
                        const int nf2 = nh * 2 + j;
                        const uint32_t off = 16384u + (uint32_t)(nrow + 16 * nf2) * 64u +
                                             ((kcB ^ swzB) << 4);
                        ldsm4(bb[j], s0 + off);
                    }
                } else {
                    const uint32_t krow = (uint32_t)(ks * 16 + 8 * ((lane >> 3) & 1) + (lane & 7));
                    const uint32_t rowo = 16384u + krow * 256u;
#pragma unroll
                    for (int j = 0; j < 2; ++j) {
                        const uint32_t c16 = (uint32_t)((wn >> 3) + (lane >> 4) + (nh * 2 + j) * 2);
                        ldsm4t(bb[j], s0 + rowo + ((c16 ^ (uint32_t)(lane & 7)) << 4));
                    }
                }
#pragma unroll
                for (int mf = 0; mf < 2; ++mf)
#pragma unroll
                    for (int j = 0; j < 2; ++j) {
                        mma16816(C[mf][nh * 4 + j * 2 + 0], aH[mf], &bb[j][0]);
                        mma16816(C[mf][nh * 4 + j * 2 + 1], aH[mf], &bb[j][2]);
                    }
#pragma unroll
                for (int mf = 0; mf < 2; ++mf)
#pragma unroll
                    for (int j = 0; j < 2; ++j) {
                        mma16816(C[mf][nh * 4 + j * 2 + 0], aL[mf], &bb[j][0]);
                        mma16816(C[mf][nh * 4 + j * 2 + 1], aL[mf], &bb[j][2]);
                    }
                // ---- Bl fragments: term Ah*Bl ----
                if constexpr (!TRB) {
                    const uint32_t kcB = (uint32_t)(ks * 2 + ((lane >> 3) & 1));
#pragma unroll
                    for (int j = 0; j < 2; ++j) {
                        const int nf2 = nh * 2 + j;
                        const uint32_t off = 24576u + (uint32_t)(nrow + 16 * nf2) * 64u +
                                             ((kcB ^ swzB) << 4);
                        ldsm4(bb[j], s0 + off);
                    }
                } else {
                    const uint32_t krow = (uint32_t)(ks * 16 + 8 * ((lane >> 3) & 1) + (lane & 7));
                    const uint32_t rowo = 24576u + krow * 256u;
#pragma unroll
                    for (int j = 0; j < 2; ++j) {
                        const uint32_t c16 = (uint32_t)((wn >> 3) + (lane >> 4) + (nh * 2 + j) * 2);
                        ldsm4t(bb[j], s0 + rowo + ((c16 ^ (uint32_t)(lane & 7)) << 4));
                    }
                }
#pragma unroll
                for (int mf = 0; mf < 2; ++mf)
#pragma unroll
                    for (int j = 0; j < 2; ++j) {
                        mma16816(C[mf][nh * 4 + j * 2 + 0], aH[mf], &bb[j][0]);
                        mma16816(C[mf][nh * 4 + j * 2 + 1], aH[mf], &bb[j][2]);
                    }
            }
        }
    }

    // ---- epilogue ----------------------------------------------------------
    const int mb = m0 + wm + (lane >> 2);
    const int nbl = wn + 2 * (lane & 3);
#pragma unroll
    for (int mf = 0; mf < 2; ++mf) {
        const size_t r0 = (size_t)(mb + 16 * mf);
#pragma unroll
        for (int nf = 0; nf < 8; ++nf) {
            const int cloc = nbl + nf * 8;
            const int c = n0 + cloc;
            const float b0 = bias_s[cloc], b1 = bias_s[cloc + 1];
            const float v0 = C[mf][nf][0] * alpha + b0;
            const float v1 = C[mf][nf][1] * alpha + b1;
            const float v2 = C[mf][nf][2] * alpha + b0;
            const float v3 = C[mf][nf][3] * alpha + b1;
            if constexpr (MODE == 0) {
                *(float2*)&Cf[r0 * ldC + c]       = make_float2(v0, v1);
                *(float2*)&Cf[(r0 + 8) * ldC + c] = make_float2(v2, v3);
            } else {
                bf16 h0, l0, h1, l1, h2, l2, h3, l3;
                split2(v0, h0, l0); split2(v1, h1, l1);
                split2(v2, h2, l2); split2(v3, h3, l3);
                *(__nv_bfloat162*)&Ch[r0 * ldC + c]       = __nv_bfloat162(h0, h1);
                *(__nv_bfloat162*)&Cl[r0 * ldC + c]       = __nv_bfloat162(l0, l1);
                *(__nv_bfloat162*)&Ch[(r0 + 8) * ldC + c] = __nv_bfloat162(h2, h3);
                *(__nv_bfloat162*)&Cl[(r0 + 8) * ldC + c] = __nv_bfloat162(l2, l3);
            }
        }
    }
}

template <bool TRA, bool TRB, int MODE>
__global__ void __launch_bounds__(256, 2)
mma_gemm(const bf16* __restrict__ Ah, const bf16* __restrict__ Al, int ldA, long long sAz,
         const bf16* __restrict__ Bh, const bf16* __restrict__ Bl, int ldB, long long sBz,
         float* __restrict__ Cf, bf16* __restrict__ Ch, bf16* __restrict__ Cl,
         int ldC, long long sCz, const float* __restrict__ bias, float alpha, int K)
{
    extern __shared__ char smem[];
    const long long z = blockIdx.z;
    gemm_body<TRA, TRB, MODE>(
        Ah + z * sAz, Al + z * sAz, ldA, Bh + z * sBz, Bl + z * sBz, ldB,
        (MODE == 0) ? Cf + z * sCz : Cf,
        (MODE == 1) ? Ch + z * sCz : Ch,
        (MODE == 1) ? Cl + z * sCz : Cl,
        ldC, bias, alpha, K, smem);
}

// ---- fused M = Wq^T Wk and N = Wo Wv, split-K=8 each (z: 0-7 M, 8-15 N) ----
// Total reduction length is 3072 -> per-slab K = 3072/8 = 384.
__global__ void __launch_bounds__(256, 2)
mn_gemm(const bf16* __restrict__ w1h, const bf16* __restrict__ w1l,
        const bf16* __restrict__ w2h, const bf16* __restrict__ w2l,
        const bf16* __restrict__ w3h, const bf16* __restrict__ w3l,
        const bf16* __restrict__ w4h, const bf16* __restrict__ w4l,
        float* __restrict__ part)
{
    extern __shared__ char smem[];
    const int z = blockIdx.z;
    float* Cf = part + (size_t)z * 1048576;
    if (z < 8) {
        const size_t o = (size_t)z * 384 * 1024;   // k-major slab offset
        gemm_body<true, true, 0>(w1h + o, w1l + o, 1024, w2h + o, w2l + o, 1024,
                                 Cf, nullptr, nullptr, 1024, nullptr, 1.0f, 384, smem);
    } else {
        const int z2 = z - 8;
        const size_t oB = (size_t)z2 * 384 * 1024; // Wv k-major slab
        gemm_body<false, true, 0>(w3h + z2 * 384, w3l + z2 * 384, 3072,
                                  w4h + oB, w4l + oB, 1024,
                                  Cf, nullptr, nullptr, 1024, nullptr, 1.0f, 384, smem);
    }
}

// ---------------------------------------------------------------------------
// prep: fused splits (X, Wq, Wk, Wo, Wv) + tvec partials + dvec partials
// ---------------------------------------------------------------------------
__global__ void __launch_bounds__(256)
prep_kernel(const float* __restrict__ x,  const float* __restrict__ Wq,
            const float* __restrict__ Wk, const float* __restrict__ Wv,
            const float* __restrict__ Wo, const float* __restrict__ bq,
            const float* __restrict__ bv,
            bf16* __restrict__ xh,  bf16* __restrict__ xl,
            bf16* __restrict__ w1h, bf16* __restrict__ w1l,
            bf16* __restrict__ w2h, bf16* __restrict__ w2l,
            bf16* __restrict__ w3h, bf16* __restrict__ w3l,
            bf16* __restrict__ w4h, bf16* __restrict__ w4l,
            float* __restrict__ tpart, float* __restrict__ dpart)
{
    __shared__ float sred[256];
    const int b = blockIdx.x;
    const int tid = threadIdx.x;

    if (b < 20480) {
        const float* src; bf16 *dh, *dl; int i0;
        if (b < 8192)       { src = x;  dh = xh;  dl = xl;  i0 = b; }
        else if (b < 11264) { src = Wq; dh = w1h; dl = w1l; i0 = b - 8192; }
        else if (b < 14336) { src = Wk; dh = w2h; dl = w2l; i0 = b - 11264; }
        else if (b < 17408) { src = Wo; dh = w3h; dl = w3l; i0 = b - 14336; }
        else                { src = Wv; dh = w4h; dl = w4l; i0 = b - 17408; }
        const int i = i0 * 256 + tid;
        const float4 v = ((const float4*)src)[i];
        bf16 h0, h1, h2, h3, l0, l1, l2, l3;
        split2(v.x, h0, l0); split2(v.y, h1, l1);
        split2(v.z, h2, l2); split2(v.w, h3, l3);
        ((__nv_bfloat162*)dh)[2 * i]     = __nv_bfloat162(h0, h1);
        ((__nv_bfloat162*)dh)[2 * i + 1] = __nv_bfloat162(h2, h3);
        ((__nv_bfloat162*)dl)[2 * i]     = __nv_bfloat162(l0, l1);
        ((__nv_bfloat162*)dl)[2 * i + 1] = __nv_bfloat162(l2, l3);
    } else if (b < 20672) {
        // tvec partials: tpart[ec][d] = sum_{e in chunk ec} Wk[e][d] * bq[e]
        const int t = b - 20480;          // 0..191
        const int ec = t / 8, dc = t % 8; // 24 e-chunks x 8 d-chunks
        const int d = dc * 128 + (tid & 127);
        const int el = tid >> 7;          // 0 or 1
        float acc = 0.0f;
#pragma unroll 8
        for (int j = 0; j < 64; ++j) {
            const int e = ec * 128 + el * 64 + j;
            acc += Wk[(size_t)e * 1024 + d] * bq[e];
        }
        sred[tid] = acc;
        __syncthreads();
        if (tid < 128) tpart[ec * 1024 + d] = sred[tid] + sred[tid + 128];
    } else {
        // dvec partials: dpart[ch][row] = sum_{e in chunk ch} Wo[row][e]*bv[e]
        const int fw = (b - 20672) * 8 + (tid >> 5);  // flat warp 0..24575
        const int row = fw / 24, ch = fw % 24;
        const int lane = tid & 31;
        const float4 a = *(const float4*)&Wo[(size_t)row * 3072 + ch * 128 + lane * 4];
        const float4 c = *(const float4*)&bv[ch * 128 + lane * 4];
        float acc = a.x * c.x + a.y * c.y + a.z * c.z + a.w * c.w;
#pragma unroll
        for (int o = 16; o > 0; o >>= 1) acc += __shfl_xor_sync(0xffffffffu, acc, o);
        if (lane == 0) dpart[ch * 1024 + row] = acc;
    }
}

// ---------------- reduce tvec/dvec partials ---------------------------------
__global__ void __launch_bounds__(256)
vec_reduce(const float* __restrict__ tpart, const float* __restrict__ dpart,
           const float* __restrict__ bo, float* __restrict__ t, float* __restrict__ dv)
{
    const int i = blockIdx.x * 256 + threadIdx.x;  // 0..2047
    if (i < 1024) {
        float a = 0.0f;
#pragma unroll
        for (int e = 0; e < 24; ++e) a += tpart[e * 1024 + i];
        t[i] = a;
    } else {
        const int j = i - 1024;
        float a = 0.0f;
#pragma unroll
        for (int e = 0; e < 24; ++e) a += dpart[e * 1024 + j];
        dv[j] = a + bo[j];
    }
}

// ---------------- combine split-K partials (8 slabs each) for M and N -------
__global__ void __launch_bounds__(256)
combine2(const float* __restrict__ part, bf16* __restrict__ mh, bf16* __restrict__ ml,
         bf16* __restrict__ nh, bf16* __restrict__ nl)
{
    const int bb = blockIdx.x;                     // 0..2047
    const int half = bb >> 10;                     // 0 = M, 1 = N
    const int i = (bb & 1023) * 256 + threadIdx.x; // float4 index, 262144 per matrix
    const float* p = part + (size_t)half * 8388608;
    float4 x = make_float4(0.f, 0.f, 0.f, 0.f);
#pragma unroll
    for (int s2 = 0; s2 < 8; ++s2) {
        const float4 a = ((const float4*)p)[i + s2 * 262144];
        x.x += a.x; x.y += a.y; x.z += a.z; x.w += a.w;
    }
    bf16* hi = half ? nh : mh;
    bf16* lo = half ? nl : ml;
    bf16 h0, h1, h2, h3, l0, l1, l2, l3;
    split2(x.x, h0, l0); split2(x.y, h1, l1);
    split2(x.z, h2, l2); split2(x.w, h3, l3);
    ((__nv_bfloat162*)hi)[2 * i]     = __nv_bfloat162(h0, h1);
    ((__nv_bfloat162*)hi)[2 * i + 1] = __nv_bfloat162(h2, h3);
    ((__nv_bfloat162*)lo)[2 * i]     = __nv_bfloat162(l0, l1);
    ((__nv_bfloat162*)lo)[2 * i + 1] = __nv_bfloat162(l2, l3);
}

// ---------------- b[r] = sum_d X[r][d] * t[d]  (warp per row) ---------------
__global__ void __launch_bounds__(256)
bvec_kernel(const float* __restrict__ X, const float* __restrict__ t,
            float* __restrict__ b)
{
    const int w = (blockIdx.x * 256 + threadIdx.x) >> 5;  // 0..8191
    const int lane = threadIdx.x & 31;
    const float* row = X + (size_t)w * 1024;
    float acc = 0.0f;
#pragma unroll
    for (int j = 0; j < 8; ++j) {
        const float4 a = *(const float4*)&row[(lane + j * 32) * 4];
        const float4 c = *(const float4*)&t[(lane + j * 32) * 4];
        acc += a.x * c.x + a.y * c.y + a.z * c.z + a.w * c.w;
    }
#pragma unroll
    for (int o = 16; o > 0; o >>= 1) acc += __shfl_xor_sync(0xffffffffu, acc, o);
    if (lane == 0) b[w] = acc;
}

// ---------------- softmax over 2048 cols (+0.125*b_m) -> bf16 hi/lo ---------
__global__ void __launch_bounds__(256)
softmax_split(const float* __restrict__ S, const float* __restrict__ bvec,
              bf16* __restrict__ ph, bf16* __restrict__ pl)
{
    const long long row = blockIdx.x;
    const float* p = S + row * 2048;
    const float* bv = bvec + ((row >> 11) << 11);
    const int t = threadIdx.x;

    float4 x0 = *(const float4*)&p[t * 4];
    float4 x1 = *(const float4*)&p[1024 + t * 4];
    const float4 c0 = *(const float4*)&bv[t * 4];
    const float4 c1 = *(const float4*)&bv[1024 + t * 4];
    x0.x += 0.125f * c0.x; x0.y += 0.125f * c0.y;
    x0.z += 0.125f * c0.z; x0.w += 0.125f * c0.w;
    x1.x += 0.125f * c1.x; x1.y += 0.125f * c1.y;
    x1.z += 0.125f * c1.z; x1.w += 0.125f * c1.w;

    float m = fmaxf(fmaxf(fmaxf(x0.x, x0.y), fmaxf(x0.z, x0.w)),
                    fmaxf(fmaxf(x1.x, x1.y), fmaxf(x1.z, x1.w)));
#pragma unroll
    for (int o = 16; o > 0; o >>= 1) m = fmaxf(m, __shfl_xor_sync(0xffffffffu, m, o));
    __shared__ float red[8];
    if ((t & 31) == 0) red[t >> 5] = m;
    __syncthreads();
    m = fmaxf(fmaxf(fmaxf(red[0], red[1]), fmaxf(red[2], red[3])),
              fmaxf(fmaxf(red[4], red[5]), fmaxf(red[6], red[7])));
    __syncthreads();

    float e[8];
    e[0] = fexp(x0.x - m); e[1] = fexp(x0.y - m);
    e[2] = fexp(x0.z - m); e[3] = fexp(x0.w - m);
    e[4] = fexp(x1.x - m); e[5] = fexp(x1.y - m);
    e[6] = fexp(x1.z - m); e[7] = fexp(x1.w - m);

    float s = ((e[0] + e[1]) + (e[2] + e[3])) + ((e[4] + e[5]) + (e[6] + e[7]));
#pragma unroll
    for (int o = 16; o > 0; o >>= 1) s += __shfl_xor_sync(0xffffffffu, s, o);
    if ((t & 31) == 0) red[t >> 5] = s;
    __syncthreads();
    const float inv = 1.0f / (((red[0] + red[1]) + (red[2] + red[3])) +
                              ((red[4] + red[5]) + (red[6] + red[7])));

    bf16* hp = ph + row * 2048;
    bf16* lp = pl + row * 2048;
#pragma unroll
    for (int g = 0; g < 2; ++g) {
        bf16 hh[4], ll[4];
#pragma unroll
        for (int j = 0; j < 4; ++j) split2(e[g * 4 + j] * inv, hh[j], ll[j]);
        const int base = g * 1024 + t * 4;
        *(__nv_bfloat162*)&hp[base]     = __nv_bfloat162(hh[0], hh[1]);
        *(__nv_bfloat162*)&hp[base + 2] = __nv_bfloat162(hh[2], hh[3]);
        *(__nv_bfloat162*)&lp[base]     = __nv_bfloat162(ll[0], ll[1]);
        *(__nv_bfloat162*)&lp[base + 2] = __nv_bfloat162(ll[2], ll[3]);
    }
}

// ---------------------------------------------------------------------------
extern "C" void kernel_launch(void* const* d_in, const int* in_sizes, int n_in,
                              void* d_out, int out_size)
{
    (void)in_sizes; (void)n_in; (void)out_size;
    const float* x  = (const float*)d_in[0];
    const float* Wq = (const float*)d_in[1];
    const float* bq = (const float*)d_in[2];
    const float* Wk = (const float*)d_in[3];
    const float* bk = (const float*)d_in[4];  (void)bk;  // cancels in softmax
    const float* Wv = (const float*)d_in[5];
    const float* bv = (const float*)d_in[6];
    const float* Wo = (const float*)d_in[7];
    const float* bo = (const float*)d_in[8];
    float* out = (float*)d_out;

    bf16 *xh, *xl, *w1h, *w1l, *w2h, *w2l, *w3h, *w3l, *w4h, *w4l;
    bf16 *mh, *ml, *nh, *nl, *xmh, *xml, *ph, *pl, *c2h, *c2l;
    float *part, *s, *tv, *bvv, *dv;
    cudaGetSymbolAddress((void**)&xh, g_xh);   cudaGetSymbolAddress((void**)&xl, g_xl);
    cudaGetSymbolAddress((void**)&w1h, g_w1h); cudaGetSymbolAddress((void**)&w1l, g_w1l);
    cudaGetSymbolAddress((void**)&w2h, g_w2h); cudaGetSymbolAddress((void**)&w2l, g_w2l);
    cudaGetSymbolAddress((void**)&w3h, g_w3h); cudaGetSymbolAddress((void**)&w3l, g_w3l);
    cudaGetSymbolAddress((void**)&w4h, g_w4h); cudaGetSymbolAddress((void**)&w4l, g_w4l);
    cudaGetSymbolAddress((void**)&part, g_part);
    cudaGetSymbolAddress((void**)&mh, g_mh);   cudaGetSymbolAddress((void**)&ml, g_ml);
    cudaGetSymbolAddress((void**)&nh, g_nh);   cudaGetSymbolAddress((void**)&nl, g_nl);
    cudaGetSymbolAddress((void**)&xmh, g_xmh); cudaGetSymbolAddress((void**)&xml, g_xml);
    cudaGetSymbolAddress((void**)&s, g_s);
    cudaGetSymbolAddress((void**)&ph, g_ph);   cudaGetSymbolAddress((void**)&pl, g_pl);
    cudaGetSymbolAddress((void**)&c2h, g_c2h); cudaGetSymbolAddress((void**)&c2l, g_c2l);
    cudaGetSymbolAddress((void**)&tv, g_tvec);
    cudaGetSymbolAddress((void**)&bvv, g_bvec);
    cudaGetSymbolAddress((void**)&dv, g_dvec);

    cudaFuncSetAttribute(mma_gemm<false, false, 0>, cudaFuncAttributeMaxDynamicSharedMemorySize, SMEM_DYN);
    cudaFuncSetAttribute(mma_gemm<false, true, 1>,  cudaFuncAttributeMaxDynamicSharedMemorySize, SMEM_DYN);
    cudaFuncSetAttribute(mn_gemm,                   cudaFuncAttributeMaxDynamicSharedMemorySize, SMEM_DYN);

    const long long QS = 2048LL * 1024, SS = 2048LL * 2048;

    // ---- fused prep: all splits + tvec/dvec partials -----------------------
    prep_kernel<<<23744, 256>>>(x, Wq, Wk, Wv, Wo, bq, bv,
                                xh, xl, w1h, w1l, w2h, w2l, w3h, w3l, w4h, w4l,
                                part, part + 32768);
    vec_reduce<<<8, 256>>>(part, part + 32768, bo, tv, dv);
    bvec_kernel<<<1024, 256>>>(x, tv, bvv);   // b = X t

    // ---- M = Wq^T Wk and N = Wo Wv, one launch, split-K=8 each -------------
    mn_gemm<<<dim3(8, 8, 16), 256, SMEM_DYN>>>(w1h, w1l, w2h, w2l,
                                               w3h, w3l, w4h, w4l, part);
    combine2<<<2048, 256>>>(part, mh, ml, nh, nl);

    // ---- XM = X * M  (B = M row-major [k][n] -> TRB) -----------------------
    mma_gemm<false, true, 1><<<dim3(8, 64, 1), 256, SMEM_DYN>>>(
        xh, xl, 1024, 0, mh, ml, 1024, 0,
        nullptr, xmh, xml, 1024, 0, nullptr, 1.0f, 1024);

    // ---- scores = 0.125 * (XM) X^T per batch -------------------------------
    mma_gemm<false, false, 0><<<dim3(16, 16, 4), 256, SMEM_DYN>>>(
        xmh, xml, 1024, QS, xh, xl, 1024, QS,
        s, nullptr, nullptr, 2048, SS, nullptr, 0.125f, 1024);

    // ---- softmax (adds 0.125*b_m) -> split probs ---------------------------
    softmax_split<<<8192, 256>>>(s, bvv, ph, pl);

    // ---- C2 = P X per batch (B = X [k][n] -> TRB) --------------------------
    mma_gemm<false, true, 1><<<dim3(8, 16, 4), 256, SMEM_DYN>>>(
        ph, pl, 2048, SS, xh, xl, 1024, QS,
        nullptr, c2h, c2l, 1024, QS, nullptr, 1.0f, 2048);

    // ---- out = C2 N^T + d --------------------------------------------------
    mma_gemm<false, false, 0><<<dim3(8, 64, 1), 256, SMEM_DYN>>>(
        c2h, c2l, 1024, 0, nh, nl, 1024, 0,
        out, nullptr, nullptr, 1024, 0, dv, 1.0f, 1024);
}